// round 6
// baseline (speedup 1.0000x reference)
#include <cuda_runtime.h>

// Problem constants (fixed by the dataset)
#define BB     16384   // batch
#define TT     60
#define II     32      // input / output feature dim
#define HH     128     // hidden dim
#define STEPS  30
#define SEQOFF 30      // x[:, 30, :] is the only x slice used

#define MT   32        // batch elements per CTA
#define NTH  256       // threads per CTA

typedef unsigned long long u64;

// ---------------------------------------------------------------------------
// Packed (transposed) weights in device-global scratch. Repacked every launch.
//   g_Wx[k][g]  = W_ih[g][k]   k in [0,32),  g in [0,384)
//   g_Wh[k][g]  = W_hh[g][k]   k in [0,128), g in [0,384)
//   g_Wot[k][i] = W_out[i][k]  k in [0,128), i in [0,32)
// ---------------------------------------------------------------------------
__device__ __align__(16) float g_Wx[32 * 384];
__device__ __align__(16) float g_Wh[128 * 384];
__device__ __align__(16) float g_Wot[128 * 32];
__device__ float g_br[128], g_bz[128], g_bin[128], g_bhn[128];

__global__ void pack_kernel(const float* __restrict__ W_ih,
                            const float* __restrict__ W_hh,
                            const float* __restrict__ W_out,
                            const float* __restrict__ b_ih,
                            const float* __restrict__ b_hh)
{
    int idx = blockIdx.x * blockDim.x + threadIdx.x;
    if (idx < 12288) {                       // Wx: 32*384
        int k = idx / 384, g = idx - k * 384;
        g_Wx[idx] = W_ih[g * 32 + k];
    }
    int i2 = idx - 12288;                    // Wh: 128*384
    if (i2 >= 0 && i2 < 49152) {
        int k = i2 / 384, g = i2 - k * 384;
        g_Wh[i2] = W_hh[g * 128 + k];
    }
    int i3 = idx - 61440;                    // Wot: 128*32
    if (i3 >= 0 && i3 < 4096) {
        int k = i3 >> 5, i = i3 & 31;
        g_Wot[i3] = W_out[i * 128 + k];
    }
    int i4 = idx - 65536;                    // biases
    if (i4 >= 0 && i4 < 128) {
        g_br[i4]  = b_ih[i4]        + b_hh[i4];
        g_bz[i4]  = b_ih[128 + i4]  + b_hh[128 + i4];
        g_bin[i4] = b_ih[256 + i4];
        g_bhn[i4] = b_hh[256 + i4];
    }
}

// ---------------------------------------------------------------------------
// Packed f32x2 helpers (FFMA2 — only reachable via PTX on sm_103a)
// ---------------------------------------------------------------------------
__device__ __forceinline__ u64 dup2(float v) {
    u64 r; asm("mov.b64 %0, {%1, %1};" : "=l"(r) : "f"(v)); return r;
}
__device__ __forceinline__ void unpack2(u64 v, float& lo, float& hi) {
    asm("mov.b64 {%0, %1}, %2;" : "=f"(lo), "=f"(hi) : "l"(v));
}
__device__ __forceinline__ u64 fma2(u64 a, u64 b, u64 c) {
    u64 d; asm("fma.rn.f32x2 %0, %1, %2, %3;" : "=l"(d) : "l"(a), "l"(b), "l"(c));
    return d;
}

__device__ __forceinline__ float sigmoid_f(float v) {
    return __fdividef(1.0f, 1.0f + __expf(-v));
}
__device__ __forceinline__ float tanh_f(float v) {
    // 1 - 2/(e^{2v}+1): exact saturation at +/-1, ~2^-21 rel err otherwise
    return 1.0f - __fdividef(2.0f, __expf(2.0f * v) + 1.0f);
}

// ---------------------------------------------------------------------------
// Main recurrent kernel. One CTA = 32 batch elements for all 30 steps.
// Activation state transposed in smem: A[buf][k][m], k in [0,160)
// (rows 0..31 = x_t, rows 32..159 = h_t), row stride 36 floats.
// Thread tile: 4 batch (m) x 4 hidden (j); j-pairs packed into f32x2.
// ---------------------------------------------------------------------------
__global__ __launch_bounds__(NTH, 2)
void gru_kernel(const float* __restrict__ x,
                const float* __restrict__ h0,
                const float* __restrict__ b_out,
                float* __restrict__ out)
{
    __shared__ float A[2][160][36];

    const int tid = threadIdx.x;
    const int b0  = blockIdx.x * MT;
    const int tm4 = (tid >> 5) << 2;   // batch offset within tile: 0,4,...,28
    const int tj  = tid & 31;          // lane: j-group / output feature
    const int j4  = tj << 2;           // hidden offset: 0,4,...,124

    // ---- prologue: x0 = x[:,30,:]  and  h0 into A[0] (transposed) ----
    for (int idx = tid; idx < MT * II; idx += NTH) {
        int m = idx >> 5, i = idx & 31;
        A[0][i][m] = x[(size_t)(b0 + m) * (TT * II) + SEQOFF * II + i];
    }
    for (int idx = tid; idx < MT * HH; idx += NTH) {
        int m = idx >> 7, k = idx & 127;
        A[0][32 + k][m] = h0[(size_t)(b0 + m) * HH + k];
    }

    float br_[4], bz_[4], bin_[4], bhn_[4];
#pragma unroll
    for (int ji = 0; ji < 4; ji++) {
        br_[ji]  = g_br[j4 + ji];
        bz_[ji]  = g_bz[j4 + ji];
        bin_[ji] = g_bin[j4 + ji];
        bhn_[ji] = g_bhn[j4 + ji];
    }
    const float bo = b_out[tj];
    __syncthreads();

    for (int t = 0; t < STEPS; t++) {
        const int cur = t & 1, nxt = cur ^ 1;

        // Accumulators: [mi][jpair], each u64 = two f32 lanes (j even/odd)
        u64 ar2[4][2], az2[4][2], ain2[4][2], ahn2[4][2];
#pragma unroll
        for (int mi = 0; mi < 4; mi++)
#pragma unroll
            for (int jp = 0; jp < 2; jp++) {
                ar2[mi][jp] = 0ULL; az2[mi][jp] = 0ULL;
                ain2[mi][jp] = 0ULL; ahn2[mi][jp] = 0ULL;
            }

        // ---- gate GEMM, x part (K = 32): accumulates r, z, i_n ----
#pragma unroll 2
        for (int k = 0; k < II; k++) {
            const float4 a = *(const float4*)&A[cur][k][tm4];   // warp-uniform
            const u64 amd[4] = {dup2(a.x), dup2(a.y), dup2(a.z), dup2(a.w)};
            const ulonglong2 wr = __ldg((const ulonglong2*)&g_Wx[k * 384 + j4]);
            const ulonglong2 wz = __ldg((const ulonglong2*)&g_Wx[k * 384 + 128 + j4]);
            const ulonglong2 wn = __ldg((const ulonglong2*)&g_Wx[k * 384 + 256 + j4]);
#pragma unroll
            for (int mi = 0; mi < 4; mi++) {
                ar2[mi][0]  = fma2(amd[mi], wr.x, ar2[mi][0]);
                ar2[mi][1]  = fma2(amd[mi], wr.y, ar2[mi][1]);
                az2[mi][0]  = fma2(amd[mi], wz.x, az2[mi][0]);
                az2[mi][1]  = fma2(amd[mi], wz.y, az2[mi][1]);
                ain2[mi][0] = fma2(amd[mi], wn.x, ain2[mi][0]);
                ain2[mi][1] = fma2(amd[mi], wn.y, ain2[mi][1]);
            }
        }

        // ---- gate GEMM, h part (K = 128): accumulates r, z, h_n ----
#pragma unroll 2
        for (int k = 0; k < HH; k++) {
            const float4 a = *(const float4*)&A[cur][32 + k][tm4];
            const u64 amd[4] = {dup2(a.x), dup2(a.y), dup2(a.z), dup2(a.w)};
            const ulonglong2 wr = __ldg((const ulonglong2*)&g_Wh[k * 384 + j4]);
            const ulonglong2 wz = __ldg((const ulonglong2*)&g_Wh[k * 384 + 128 + j4]);
            const ulonglong2 wn = __ldg((const ulonglong2*)&g_Wh[k * 384 + 256 + j4]);
#pragma unroll
            for (int mi = 0; mi < 4; mi++) {
                ar2[mi][0]  = fma2(amd[mi], wr.x, ar2[mi][0]);
                ar2[mi][1]  = fma2(amd[mi], wr.y, ar2[mi][1]);
                az2[mi][0]  = fma2(amd[mi], wz.x, az2[mi][0]);
                az2[mi][1]  = fma2(amd[mi], wz.y, az2[mi][1]);
                ahn2[mi][0] = fma2(amd[mi], wn.x, ahn2[mi][0]);
                ahn2[mi][1] = fma2(amd[mi], wn.y, ahn2[mi][1]);
            }
        }

        // ---- activations + h_new -> A[nxt] hidden rows ----
#pragma unroll
        for (int jp = 0; jp < 2; jp++) {
            const int j0 = j4 + 2 * jp;
            const float4 he = *(const float4*)&A[cur][32 + j0][tm4];
            const float4 hoq = *(const float4*)&A[cur][32 + j0 + 1][tm4];
            const float he_[4] = {he.x, he.y, he.z, he.w};
            const float ho_[4] = {hoq.x, hoq.y, hoq.z, hoq.w};
            float hn0[4], hn1[4];
#pragma unroll
            for (int mi = 0; mi < 4; mi++) {
                float vr0, vr1, vz0, vz1, vi0, vi1, vh0, vh1;
                unpack2(ar2[mi][jp], vr0, vr1);
                unpack2(az2[mi][jp], vz0, vz1);
                unpack2(ain2[mi][jp], vi0, vi1);
                unpack2(ahn2[mi][jp], vh0, vh1);
                {   // j = j0 (even lane)
                    const int ji = 2 * jp;
                    float r = sigmoid_f(vr0 + br_[ji]);
                    float z = sigmoid_f(vz0 + bz_[ji]);
                    float n = tanh_f(fmaf(r, vh0 + bhn_[ji], vi0 + bin_[ji]));
                    hn0[mi] = n + z * (he_[mi] - n);
                }
                {   // j = j0+1 (odd lane)
                    const int ji = 2 * jp + 1;
                    float r = sigmoid_f(vr1 + br_[ji]);
                    float z = sigmoid_f(vz1 + bz_[ji]);
                    float n = tanh_f(fmaf(r, vh1 + bhn_[ji], vi1 + bin_[ji]));
                    hn1[mi] = n + z * (ho_[mi] - n);
                }
            }
            *(float4*)&A[nxt][32 + j0][tm4] =
                make_float4(hn0[0], hn0[1], hn0[2], hn0[3]);
            *(float4*)&A[nxt][32 + j0 + 1][tm4] =
                make_float4(hn1[0], hn1[1], hn1[2], hn1[3]);
        }
        __syncthreads();   // Hnew complete

        // ---- output GEMM: y = h_new @ W_out^T + b_out (lane = feature i) ----
        // Packed over batch pairs: (m0,m1) and (m2,m3) are natural smem pairs.
        u64 y01 = dup2(bo), y23 = dup2(bo);
#pragma unroll 4
        for (int k = 0; k < HH; k++) {
            const ulonglong2 hv = *(const ulonglong2*)&A[nxt][32 + k][tm4];
            const u64 wd = dup2(__ldg(&g_Wot[(k << 5) + tj]));
            y01 = fma2(hv.x, wd, y01);
            y23 = fma2(hv.y, wd, y23);
        }
        float yv[4];
        unpack2(y01, yv[0], yv[1]);
        unpack2(y23, yv[2], yv[3]);
#pragma unroll
        for (int mi = 0; mi < 4; mi++) {
            out[((size_t)(b0 + tm4 + mi) * STEPS + t) * II + tj] = yv[mi];
            A[nxt][tj][tm4 + mi] = yv[mi];   // y feeds back as x_{t+1}
        }
        __syncthreads();   // x rows of A[nxt] complete before next step
    }
}

// ---------------------------------------------------------------------------
// Harness entry point
// ---------------------------------------------------------------------------
extern "C" void kernel_launch(void* const* d_in, const int* in_sizes, int n_in,
                              void* d_out, int out_size)
{
    const float* x     = (const float*)d_in[0];
    const float* h     = (const float*)d_in[1];
    const float* W_ih  = (const float*)d_in[2];
    const float* W_hh  = (const float*)d_in[3];
    const float* b_ih  = (const float*)d_in[4];
    const float* b_hh  = (const float*)d_in[5];
    const float* W_out = (const float*)d_in[6];
    const float* b_out = (const float*)d_in[7];
    float* out = (float*)d_out;

    pack_kernel<<<257, 256>>>(W_ih, W_hh, W_out, b_ih, b_hh);
    gru_kernel<<<BB / MT, NTH>>>(x, h, b_out, out);
}

// round 7
// speedup vs baseline: 1.0041x; 1.0041x over previous
#include <cuda_runtime.h>

// Problem constants (fixed by the dataset)
#define BB     16384   // batch
#define TT     60
#define II     32      // input / output feature dim
#define HH     128     // hidden dim
#define STEPS  30
#define SEQOFF 30      // x[:, 30, :] is the only x slice used

#define MT   32        // batch elements per CTA
#define NTH  256       // threads per CTA

typedef unsigned long long u64;

// ---------------------------------------------------------------------------
// Packed (transposed) weights in device-global scratch. Repacked every launch.
//   g_Wx[k][g]  = W_ih[g][k]   k in [0,32),  g in [0,384)
//   g_Wh[k][g]  = W_hh[g][k]   k in [0,128), g in [0,384)
//   g_Wot[k][i] = W_out[i][k]  k in [0,128), i in [0,32)
// ---------------------------------------------------------------------------
__device__ __align__(16) float g_Wx[32 * 384];
__device__ __align__(16) float g_Wh[128 * 384];
__device__ __align__(16) float g_Wot[128 * 32];
__device__ float g_br[128], g_bz[128], g_bin[128], g_bhn[128];

__global__ void pack_kernel(const float* __restrict__ W_ih,
                            const float* __restrict__ W_hh,
                            const float* __restrict__ W_out,
                            const float* __restrict__ b_ih,
                            const float* __restrict__ b_hh)
{
    int idx = blockIdx.x * blockDim.x + threadIdx.x;
    if (idx < 12288) {                       // Wx: 32*384
        int k = idx / 384, g = idx - k * 384;
        g_Wx[idx] = W_ih[g * 32 + k];
    }
    int i2 = idx - 12288;                    // Wh: 128*384
    if (i2 >= 0 && i2 < 49152) {
        int k = i2 / 384, g = i2 - k * 384;
        g_Wh[i2] = W_hh[g * 128 + k];
    }
    int i3 = idx - 61440;                    // Wot: 128*32
    if (i3 >= 0 && i3 < 4096) {
        int k = i3 >> 5, i = i3 & 31;
        g_Wot[i3] = W_out[i * 128 + k];
    }
    int i4 = idx - 65536;                    // biases
    if (i4 >= 0 && i4 < 128) {
        g_br[i4]  = b_ih[i4]        + b_hh[i4];
        g_bz[i4]  = b_ih[128 + i4]  + b_hh[128 + i4];
        g_bin[i4] = b_ih[256 + i4];
        g_bhn[i4] = b_hh[256 + i4];
    }
}

// ---------------------------------------------------------------------------
// Packed f32x2 helpers (FFMA2 — only reachable via PTX on sm_103a)
// ---------------------------------------------------------------------------
__device__ __forceinline__ u64 dup2(float v) {
    u64 r; asm("mov.b64 %0, {%1, %1};" : "=l"(r) : "f"(v)); return r;
}
__device__ __forceinline__ void unpack2(u64 v, float& lo, float& hi) {
    asm("mov.b64 {%0, %1}, %2;" : "=f"(lo), "=f"(hi) : "l"(v));
}
__device__ __forceinline__ u64 fma2(u64 a, u64 b, u64 c) {
    u64 d; asm("fma.rn.f32x2 %0, %1, %2, %3;" : "=l"(d) : "l"(a), "l"(b), "l"(c));
    return d;
}

__device__ __forceinline__ float sigmoid_f(float v) {
    return __fdividef(1.0f, 1.0f + __expf(-v));
}
__device__ __forceinline__ float tanh_f(float v) {
    // 1 - 2/(e^{2v}+1): exact saturation at +/-1, ~2^-21 rel err otherwise
    return 1.0f - __fdividef(2.0f, __expf(2.0f * v) + 1.0f);
}

// ---------------------------------------------------------------------------
// Main recurrent kernel. One CTA = 32 batch elements for all 30 steps.
// Activation state transposed in smem: A[buf][k][m], k in [0,160)
// (rows 0..31 = x_t, rows 32..159 = h_t), row stride 36 floats.
// Thread tile: 4 batch (m) x 4 hidden (j); j-pairs packed into f32x2.
// ---------------------------------------------------------------------------
__global__ __launch_bounds__(NTH, 2)
void gru_kernel(const float* __restrict__ x,
                const float* __restrict__ h0,
                const float* __restrict__ b_out,
                float* __restrict__ out)
{
    __shared__ float A[2][160][36];

    const int tid = threadIdx.x;
    const int b0  = blockIdx.x * MT;
    const int tm4 = (tid >> 5) << 2;   // batch offset within tile: 0,4,...,28
    const int tj  = tid & 31;          // lane: j-group / output feature
    const int j4  = tj << 2;           // hidden offset: 0,4,...,124

    // ---- prologue: x0 = x[:,30,:]  and  h0 into A[0] (transposed) ----
    for (int idx = tid; idx < MT * II; idx += NTH) {
        int m = idx >> 5, i = idx & 31;
        A[0][i][m] = x[(size_t)(b0 + m) * (TT * II) + SEQOFF * II + i];
    }
    for (int idx = tid; idx < MT * HH; idx += NTH) {
        int m = idx >> 7, k = idx & 127;
        A[0][32 + k][m] = h0[(size_t)(b0 + m) * HH + k];
    }

    float br_[4], bz_[4], bin_[4], bhn_[4];
#pragma unroll
    for (int ji = 0; ji < 4; ji++) {
        br_[ji]  = g_br[j4 + ji];
        bz_[ji]  = g_bz[j4 + ji];
        bin_[ji] = g_bin[j4 + ji];
        bhn_[ji] = g_bhn[j4 + ji];
    }
    const float bo = b_out[tj];
    __syncthreads();

    for (int t = 0; t < STEPS; t++) {
        const int cur = t & 1, nxt = cur ^ 1;

        // Accumulators: [mi][jpair], each u64 = two f32 lanes (j even/odd)
        u64 ar2[4][2], az2[4][2], ain2[4][2], ahn2[4][2];
#pragma unroll
        for (int mi = 0; mi < 4; mi++)
#pragma unroll
            for (int jp = 0; jp < 2; jp++) {
                ar2[mi][jp] = 0ULL; az2[mi][jp] = 0ULL;
                ain2[mi][jp] = 0ULL; ahn2[mi][jp] = 0ULL;
            }

        // ---- gate GEMM, x part (K = 32): accumulates r, z, i_n ----
#pragma unroll 2
        for (int k = 0; k < II; k++) {
            const float4 a = *(const float4*)&A[cur][k][tm4];   // warp-uniform
            const u64 amd[4] = {dup2(a.x), dup2(a.y), dup2(a.z), dup2(a.w)};
            const ulonglong2 wr = __ldg((const ulonglong2*)&g_Wx[k * 384 + j4]);
            const ulonglong2 wz = __ldg((const ulonglong2*)&g_Wx[k * 384 + 128 + j4]);
            const ulonglong2 wn = __ldg((const ulonglong2*)&g_Wx[k * 384 + 256 + j4]);
#pragma unroll
            for (int mi = 0; mi < 4; mi++) {
                ar2[mi][0]  = fma2(amd[mi], wr.x, ar2[mi][0]);
                ar2[mi][1]  = fma2(amd[mi], wr.y, ar2[mi][1]);
                az2[mi][0]  = fma2(amd[mi], wz.x, az2[mi][0]);
                az2[mi][1]  = fma2(amd[mi], wz.y, az2[mi][1]);
                ain2[mi][0] = fma2(amd[mi], wn.x, ain2[mi][0]);
                ain2[mi][1] = fma2(amd[mi], wn.y, ain2[mi][1]);
            }
        }

        // ---- gate GEMM, h part (K = 128): accumulates r, z, h_n ----
#pragma unroll 2
        for (int k = 0; k < HH; k++) {
            const float4 a = *(const float4*)&A[cur][32 + k][tm4];
            const u64 amd[4] = {dup2(a.x), dup2(a.y), dup2(a.z), dup2(a.w)};
            const ulonglong2 wr = __ldg((const ulonglong2*)&g_Wh[k * 384 + j4]);
            const ulonglong2 wz = __ldg((const ulonglong2*)&g_Wh[k * 384 + 128 + j4]);
            const ulonglong2 wn = __ldg((const ulonglong2*)&g_Wh[k * 384 + 256 + j4]);
#pragma unroll
            for (int mi = 0; mi < 4; mi++) {
                ar2[mi][0]  = fma2(amd[mi], wr.x, ar2[mi][0]);
                ar2[mi][1]  = fma2(amd[mi], wr.y, ar2[mi][1]);
                az2[mi][0]  = fma2(amd[mi], wz.x, az2[mi][0]);
                az2[mi][1]  = fma2(amd[mi], wz.y, az2[mi][1]);
                ahn2[mi][0] = fma2(amd[mi], wn.x, ahn2[mi][0]);
                ahn2[mi][1] = fma2(amd[mi], wn.y, ahn2[mi][1]);
            }
        }

        // ---- activations + h_new -> A[nxt] hidden rows ----
#pragma unroll
        for (int jp = 0; jp < 2; jp++) {
            const int j0 = j4 + 2 * jp;
            const float4 he = *(const float4*)&A[cur][32 + j0][tm4];
            const float4 hoq = *(const float4*)&A[cur][32 + j0 + 1][tm4];
            const float he_[4] = {he.x, he.y, he.z, he.w};
            const float ho_[4] = {hoq.x, hoq.y, hoq.z, hoq.w};
            float hn0[4], hn1[4];
#pragma unroll
            for (int mi = 0; mi < 4; mi++) {
                float vr0, vr1, vz0, vz1, vi0, vi1, vh0, vh1;
                unpack2(ar2[mi][jp], vr0, vr1);
                unpack2(az2[mi][jp], vz0, vz1);
                unpack2(ain2[mi][jp], vi0, vi1);
                unpack2(ahn2[mi][jp], vh0, vh1);
                {   // j = j0 (even lane)
                    const int ji = 2 * jp;
                    float r = sigmoid_f(vr0 + br_[ji]);
                    float z = sigmoid_f(vz0 + bz_[ji]);
                    float n = tanh_f(fmaf(r, vh0 + bhn_[ji], vi0 + bin_[ji]));
                    hn0[mi] = n + z * (he_[mi] - n);
                }
                {   // j = j0+1 (odd lane)
                    const int ji = 2 * jp + 1;
                    float r = sigmoid_f(vr1 + br_[ji]);
                    float z = sigmoid_f(vz1 + bz_[ji]);
                    float n = tanh_f(fmaf(r, vh1 + bhn_[ji], vi1 + bin_[ji]));
                    hn1[mi] = n + z * (ho_[mi] - n);
                }
            }
            *(float4*)&A[nxt][32 + j0][tm4] =
                make_float4(hn0[0], hn0[1], hn0[2], hn0[3]);
            *(float4*)&A[nxt][32 + j0 + 1][tm4] =
                make_float4(hn1[0], hn1[1], hn1[2], hn1[3]);
        }
        __syncthreads();   // Hnew complete

        // ---- output GEMM: y = h_new @ W_out^T + b_out (lane = feature i) ----
        // Packed over batch pairs: (m0,m1) and (m2,m3) are natural smem pairs.
        u64 y01 = dup2(bo), y23 = dup2(bo);
#pragma unroll 4
        for (int k = 0; k < HH; k++) {
            const ulonglong2 hv = *(const ulonglong2*)&A[nxt][32 + k][tm4];
            const u64 wd = dup2(__ldg(&g_Wot[(k << 5) + tj]));
            y01 = fma2(hv.x, wd, y01);
            y23 = fma2(hv.y, wd, y23);
        }
        float yv[4];
        unpack2(y01, yv[0], yv[1]);
        unpack2(y23, yv[2], yv[3]);
#pragma unroll
        for (int mi = 0; mi < 4; mi++) {
            out[((size_t)(b0 + tm4 + mi) * STEPS + t) * II + tj] = yv[mi];
            A[nxt][tj][tm4 + mi] = yv[mi];   // y feeds back as x_{t+1}
        }
        __syncthreads();   // x rows of A[nxt] complete before next step
    }
}

// ---------------------------------------------------------------------------
// Harness entry point
// ---------------------------------------------------------------------------
extern "C" void kernel_launch(void* const* d_in, const int* in_sizes, int n_in,
                              void* d_out, int out_size)
{
    const float* x     = (const float*)d_in[0];
    const float* h     = (const float*)d_in[1];
    const float* W_ih  = (const float*)d_in[2];
    const float* W_hh  = (const float*)d_in[3];
    const float* b_ih  = (const float*)d_in[4];
    const float* b_hh  = (const float*)d_in[5];
    const float* W_out = (const float*)d_in[6];
    const float* b_out = (const float*)d_in[7];
    float* out = (float*)d_out;

    pack_kernel<<<257, 256>>>(W_ih, W_hh, W_out, b_ih, b_hh);
    gru_kernel<<<BB / MT, NTH>>>(x, h, b_out, out);
}

// round 9
// speedup vs baseline: 1.0086x; 1.0044x over previous
#include <cuda_runtime.h>

// Problem constants (fixed by the dataset)
#define BB     16384   // batch
#define TT     60
#define II     32      // input / output feature dim
#define HH     128     // hidden dim
#define STEPS  30
#define SEQOFF 30      // x[:, 30, :] is the only x slice used

#define MT   32        // batch elements per CTA
#define NTH  256       // threads per CTA

typedef unsigned long long u64;

// ---------------------------------------------------------------------------
// Packed (transposed) weights in device-global scratch. Repacked every launch.
//   g_Wx[k][g]  = W_ih[g][k]   k in [0,32),  g in [0,384)
//   g_Wh[k][g]  = W_hh[g][k]   k in [0,128), g in [0,384)
//   g_Wot[k][i] = W_out[i][k]  k in [0,128), i in [0,32)
// ---------------------------------------------------------------------------
__device__ __align__(16) float g_Wx[32 * 384];
__device__ __align__(16) float g_Wh[128 * 384];
__device__ __align__(16) float g_Wot[128 * 32];
__device__ float g_br[128], g_bz[128], g_bin[128], g_bhn[128];

__global__ void pack_kernel(const float* __restrict__ W_ih,
                            const float* __restrict__ W_hh,
                            const float* __restrict__ W_out,
                            const float* __restrict__ b_ih,
                            const float* __restrict__ b_hh)
{
    int idx = blockIdx.x * blockDim.x + threadIdx.x;
    if (idx < 12288) {                       // Wx: 32*384
        int k = idx / 384, g = idx - k * 384;
        g_Wx[idx] = W_ih[g * 32 + k];
    }
    int i2 = idx - 12288;                    // Wh: 128*384
    if (i2 >= 0 && i2 < 49152) {
        int k = i2 / 384, g = i2 - k * 384;
        g_Wh[i2] = W_hh[g * 128 + k];
    }
    int i3 = idx - 61440;                    // Wot: 128*32
    if (i3 >= 0 && i3 < 4096) {
        int k = i3 >> 5, i = i3 & 31;
        g_Wot[i3] = W_out[i * 128 + k];
    }
    int i4 = idx - 65536;                    // biases
    if (i4 >= 0 && i4 < 128) {
        g_br[i4]  = b_ih[i4]        + b_hh[i4];
        g_bz[i4]  = b_ih[128 + i4]  + b_hh[128 + i4];
        g_bin[i4] = b_ih[256 + i4];
        g_bhn[i4] = b_hh[256 + i4];
    }
}

// ---------------------------------------------------------------------------
// Packed f32x2 helpers (FFMA2 — only reachable via PTX on sm_103a)
// ---------------------------------------------------------------------------
__device__ __forceinline__ u64 dup2(float v) {
    u64 r; asm("mov.b64 %0, {%1, %1};" : "=l"(r) : "f"(v)); return r;
}
__device__ __forceinline__ void unpack2(u64 v, float& lo, float& hi) {
    asm("mov.b64 {%0, %1}, %2;" : "=f"(lo), "=f"(hi) : "l"(v));
}
__device__ __forceinline__ u64 fma2(u64 a, u64 b, u64 c) {
    u64 d; asm("fma.rn.f32x2 %0, %1, %2, %3;" : "=l"(d) : "l"(a), "l"(b), "l"(c));
    return d;
}

__device__ __forceinline__ float sigmoid_f(float v) {
    return __fdividef(1.0f, 1.0f + __expf(-v));
}
__device__ __forceinline__ float tanh_f(float v) {
    // 1 - 2/(e^{2v}+1): exact saturation at +/-1, ~2^-21 rel err otherwise
    return 1.0f - __fdividef(2.0f, __expf(2.0f * v) + 1.0f);
}

// ---------------------------------------------------------------------------
// Main recurrent kernel. One CTA = 32 batch elements for all 30 steps.
// Activation state transposed in smem: A[buf][k][m], k in [0,160)
// (rows 0..31 = x_t, rows 32..159 = h_t), row stride 36 floats.
// Thread tile: 4 batch (m) x 4 hidden (j); j-pairs packed into f32x2.
// ---------------------------------------------------------------------------
__global__ __launch_bounds__(NTH, 2)
void gru_kernel(const float* __restrict__ x,
                const float* __restrict__ h0,
                const float* __restrict__ b_out,
                float* __restrict__ out)
{
    __shared__ float A[2][160][36];

    const int tid = threadIdx.x;
    const int b0  = blockIdx.x * MT;
    const int tm4 = (tid >> 5) << 2;   // batch offset within tile: 0,4,...,28
    const int tj  = tid & 31;          // lane: j-group / output feature
    const int j4  = tj << 2;           // hidden offset: 0,4,...,124

    // ---- prologue: x0 = x[:,30,:]  and  h0 into A[0] (transposed) ----
    for (int idx = tid; idx < MT * II; idx += NTH) {
        int m = idx >> 5, i = idx & 31;
        A[0][i][m] = x[(size_t)(b0 + m) * (TT * II) + SEQOFF * II + i];
    }
    for (int idx = tid; idx < MT * HH; idx += NTH) {
        int m = idx >> 7, k = idx & 127;
        A[0][32 + k][m] = h0[(size_t)(b0 + m) * HH + k];
    }

    float br_[4], bz_[4], bin_[4], bhn_[4];
#pragma unroll
    for (int ji = 0; ji < 4; ji++) {
        br_[ji]  = g_br[j4 + ji];
        bz_[ji]  = g_bz[j4 + ji];
        bin_[ji] = g_bin[j4 + ji];
        bhn_[ji] = g_bhn[j4 + ji];
    }
    const float bo = b_out[tj];
    __syncthreads();

    for (int t = 0; t < STEPS; t++) {
        const int cur = t & 1, nxt = cur ^ 1;

        // Accumulators: [mi][jpair], each u64 = two f32 lanes (j even/odd)
        u64 ar2[4][2], az2[4][2], ain2[4][2], ahn2[4][2];
#pragma unroll
        for (int mi = 0; mi < 4; mi++)
#pragma unroll
            for (int jp = 0; jp < 2; jp++) {
                ar2[mi][jp] = 0ULL; az2[mi][jp] = 0ULL;
                ain2[mi][jp] = 0ULL; ahn2[mi][jp] = 0ULL;
            }

        // ---- gate GEMM, x part (K = 32): accumulates r, z, i_n ----
#pragma unroll 2
        for (int k = 0; k < II; k++) {
            const float4 a = *(const float4*)&A[cur][k][tm4];   // warp-uniform
            const u64 amd[4] = {dup2(a.x), dup2(a.y), dup2(a.z), dup2(a.w)};
            const ulonglong2 wr = __ldg((const ulonglong2*)&g_Wx[k * 384 + j4]);
            const ulonglong2 wz = __ldg((const ulonglong2*)&g_Wx[k * 384 + 128 + j4]);
            const ulonglong2 wn = __ldg((const ulonglong2*)&g_Wx[k * 384 + 256 + j4]);
#pragma unroll
            for (int mi = 0; mi < 4; mi++) {
                ar2[mi][0]  = fma2(amd[mi], wr.x, ar2[mi][0]);
                ar2[mi][1]  = fma2(amd[mi], wr.y, ar2[mi][1]);
                az2[mi][0]  = fma2(amd[mi], wz.x, az2[mi][0]);
                az2[mi][1]  = fma2(amd[mi], wz.y, az2[mi][1]);
                ain2[mi][0] = fma2(amd[mi], wn.x, ain2[mi][0]);
                ain2[mi][1] = fma2(amd[mi], wn.y, ain2[mi][1]);
            }
        }

        // ---- gate GEMM, h part (K = 128): accumulates r, z, h_n ----
#pragma unroll 2
        for (int k = 0; k < HH; k++) {
            const float4 a = *(const float4*)&A[cur][32 + k][tm4];
            const u64 amd[4] = {dup2(a.x), dup2(a.y), dup2(a.z), dup2(a.w)};
            const ulonglong2 wr = __ldg((const ulonglong2*)&g_Wh[k * 384 + j4]);
            const ulonglong2 wz = __ldg((const ulonglong2*)&g_Wh[k * 384 + 128 + j4]);
            const ulonglong2 wn = __ldg((const ulonglong2*)&g_Wh[k * 384 + 256 + j4]);
#pragma unroll
            for (int mi = 0; mi < 4; mi++) {
                ar2[mi][0]  = fma2(amd[mi], wr.x, ar2[mi][0]);
                ar2[mi][1]  = fma2(amd[mi], wr.y, ar2[mi][1]);
                az2[mi][0]  = fma2(amd[mi], wz.x, az2[mi][0]);
                az2[mi][1]  = fma2(amd[mi], wz.y, az2[mi][1]);
                ahn2[mi][0] = fma2(amd[mi], wn.x, ahn2[mi][0]);
                ahn2[mi][1] = fma2(amd[mi], wn.y, ahn2[mi][1]);
            }
        }

        // ---- activations + h_new -> A[nxt] hidden rows ----
#pragma unroll
        for (int jp = 0; jp < 2; jp++) {
            const int j0 = j4 + 2 * jp;
            const float4 he = *(const float4*)&A[cur][32 + j0][tm4];
            const float4 hoq = *(const float4*)&A[cur][32 + j0 + 1][tm4];
            const float he_[4] = {he.x, he.y, he.z, he.w};
            const float ho_[4] = {hoq.x, hoq.y, hoq.z, hoq.w};
            float hn0[4], hn1[4];
#pragma unroll
            for (int mi = 0; mi < 4; mi++) {
                float vr0, vr1, vz0, vz1, vi0, vi1, vh0, vh1;
                unpack2(ar2[mi][jp], vr0, vr1);
                unpack2(az2[mi][jp], vz0, vz1);
                unpack2(ain2[mi][jp], vi0, vi1);
                unpack2(ahn2[mi][jp], vh0, vh1);
                {   // j = j0 (even lane)
                    const int ji = 2 * jp;
                    float r = sigmoid_f(vr0 + br_[ji]);
                    float z = sigmoid_f(vz0 + bz_[ji]);
                    float n = tanh_f(fmaf(r, vh0 + bhn_[ji], vi0 + bin_[ji]));
                    hn0[mi] = n + z * (he_[mi] - n);
                }
                {   // j = j0+1 (odd lane)
                    const int ji = 2 * jp + 1;
                    float r = sigmoid_f(vr1 + br_[ji]);
                    float z = sigmoid_f(vz1 + bz_[ji]);
                    float n = tanh_f(fmaf(r, vh1 + bhn_[ji], vi1 + bin_[ji]));
                    hn1[mi] = n + z * (ho_[mi] - n);
                }
            }
            *(float4*)&A[nxt][32 + j0][tm4] =
                make_float4(hn0[0], hn0[1], hn0[2], hn0[3]);
            *(float4*)&A[nxt][32 + j0 + 1][tm4] =
                make_float4(hn1[0], hn1[1], hn1[2], hn1[3]);
        }
        __syncthreads();   // Hnew complete

        // ---- output GEMM: y = h_new @ W_out^T + b_out (lane = feature i) ----
        // Packed over batch pairs: (m0,m1) and (m2,m3) are natural smem pairs.
        u64 y01 = dup2(bo), y23 = dup2(bo);
#pragma unroll 4
        for (int k = 0; k < HH; k++) {
            const ulonglong2 hv = *(const ulonglong2*)&A[nxt][32 + k][tm4];
            const u64 wd = dup2(__ldg(&g_Wot[(k << 5) + tj]));
            y01 = fma2(hv.x, wd, y01);
            y23 = fma2(hv.y, wd, y23);
        }
        float yv[4];
        unpack2(y01, yv[0], yv[1]);
        unpack2(y23, yv[2], yv[3]);
#pragma unroll
        for (int mi = 0; mi < 4; mi++) {
            out[((size_t)(b0 + tm4 + mi) * STEPS + t) * II + tj] = yv[mi];
            A[nxt][tj][tm4 + mi] = yv[mi];   // y feeds back as x_{t+1}
        }
        __syncthreads();   // x rows of A[nxt] complete before next step
    }
}

// ---------------------------------------------------------------------------
// Harness entry point
// ---------------------------------------------------------------------------
extern "C" void kernel_launch(void* const* d_in, const int* in_sizes, int n_in,
                              void* d_out, int out_size)
{
    const float* x     = (const float*)d_in[0];
    const float* h     = (const float*)d_in[1];
    const float* W_ih  = (const float*)d_in[2];
    const float* W_hh  = (const float*)d_in[3];
    const float* b_ih  = (const float*)d_in[4];
    const float* b_hh  = (const float*)d_in[5];
    const float* W_out = (const float*)d_in[6];
    const float* b_out = (const float*)d_in[7];
    float* out = (float*)d_out;

    pack_kernel<<<257, 256>>>(W_ih, W_hh, W_out, b_ih, b_hh);
    gru_kernel<<<BB / MT, NTH>>>(x, h, b_out, out);
}

// round 12
// speedup vs baseline: 3.9586x; 3.9248x over previous
#include <cuda_runtime.h>
#include <cuda_bf16.h>

// Problem constants
#define BB     16384
#define TT     60
#define II     32
#define HH     128
#define STEPS  30
#define SEQOFF 30

#define MT    32       // batch rows per CTA (2 m16 tiles)
#define NTH   256
#define NWARP 8

typedef unsigned int u32;

// ---------------------------------------------------------------------------
// Fragment-packed weights (uint4 = {bhi0, bhi1, blo0, blo1} per lane).
// Gate B matrix: B[k][col], k in [0,160) (0-31 = x-part, 32-159 = h-part),
// col = gate*128 + j with gate 0=r,1=z,2=n.
// g_B[((w*10 + kt)*6 + tau)*32 + lane]; tau: 0,1=r 2,3=z 4,5=n; nt2 = tau&1.
// g_Wo[(kt*4 + nt)*32 + lane] for y = h @ W_out^T (B[k][i] = W_out[i][k]).
// ---------------------------------------------------------------------------
__device__ uint4 g_B[15360];
__device__ uint4 g_Wo[1024];
__device__ float g_br[128], g_bz[128], g_bin[128], g_bhn[128];

__device__ __forceinline__ u32 packhl(float a, float b, u32& lo) {
    u32 h0 = (u32)__bfloat16_as_ushort(__float2bfloat16(a));
    u32 h1 = (u32)__bfloat16_as_ushort(__float2bfloat16(b));
    float r0 = a - __uint_as_float(h0 << 16);
    float r1 = b - __uint_as_float(h1 << 16);
    u32 l0 = (u32)__bfloat16_as_ushort(__float2bfloat16(r0));
    u32 l1 = (u32)__bfloat16_as_ushort(__float2bfloat16(r1));
    lo = l0 | (l1 << 16);
    return h0 | (h1 << 16);
}

__global__ void pack_kernel(const float* __restrict__ W_ih,
                            const float* __restrict__ W_hh,
                            const float* __restrict__ W_out,
                            const float* __restrict__ b_ih,
                            const float* __restrict__ b_hh)
{
    int idx = blockIdx.x * blockDim.x + threadIdx.x;
    if (idx < 15360) {                       // gate weight fragments
        int lane = idx & 31, tau = (idx >> 5) % 6, kt = (idx / 192) % 10, w = idx / 1920;
        int gate = tau >> 1, nt2 = tau & 1;
        int n = lane >> 2, tg = lane & 3;
        int col = gate * 128 + 16 * w + 8 * nt2 + n;   // gate output row
        float e[4];
#pragma unroll
        for (int q = 0; q < 4; q++) {
            int k = kt * 16 + 2 * tg + (q & 1) + 8 * (q >> 1);
            e[q] = (k < 32) ? W_ih[col * 32 + k] : W_hh[col * 128 + (k - 32)];
        }
        u32 lo0, lo1;
        u32 hi0 = packhl(e[0], e[1], lo0);
        u32 hi1 = packhl(e[2], e[3], lo1);
        g_B[idx] = make_uint4(hi0, hi1, lo0, lo1);
    }
    int i2 = idx - 15360;
    if (i2 >= 0 && i2 < 1024) {              // W_out fragments
        int lane = i2 & 31, nt = (i2 >> 5) & 3, kt = i2 >> 7;
        int i = nt * 8 + (lane >> 2), tg = lane & 3;
        float e[4];
#pragma unroll
        for (int q = 0; q < 4; q++) {
            int k = kt * 16 + 2 * tg + (q & 1) + 8 * (q >> 1);
            e[q] = W_out[i * 128 + k];
        }
        u32 lo0, lo1;
        u32 hi0 = packhl(e[0], e[1], lo0);
        u32 hi1 = packhl(e[2], e[3], lo1);
        g_Wo[i2] = make_uint4(hi0, hi1, lo0, lo1);
    }
    int i4 = idx - 16384;
    if (i4 >= 0 && i4 < 128) {
        g_br[i4]  = b_ih[i4]       + b_hh[i4];
        g_bz[i4]  = b_ih[128 + i4] + b_hh[128 + i4];
        g_bin[i4] = b_ih[256 + i4];
        g_bhn[i4] = b_hh[256 + i4];
    }
}

__device__ __forceinline__ void mma_bf16(float (&d)[4], const uint4& a, u32 b0, u32 b1) {
    asm("mma.sync.aligned.m16n8k16.row.col.f32.bf16.bf16.f32 "
        "{%0,%1,%2,%3},{%4,%5,%6,%7},{%8,%9},{%0,%1,%2,%3};"
        : "+f"(d[0]), "+f"(d[1]), "+f"(d[2]), "+f"(d[3])
        : "r"(a.x), "r"(a.y), "r"(a.z), "r"(a.w), "r"(b0), "r"(b1));
}

// 3-pass split MMA into two m-tiles' accumulators with one weight fragment
__device__ __forceinline__ void mma_pair(float (&d0)[4], float (&d1)[4],
                                         const uint4& A0h, const uint4& A0l,
                                         const uint4& A1h, const uint4& A1l,
                                         const uint4& wf) {
    mma_bf16(d0, A0h, wf.x, wf.y);
    mma_bf16(d0, A0l, wf.x, wf.y);
    mma_bf16(d0, A0h, wf.z, wf.w);
    mma_bf16(d1, A1h, wf.x, wf.y);
    mma_bf16(d1, A1l, wf.x, wf.y);
    mma_bf16(d1, A1h, wf.z, wf.w);
}

__device__ __forceinline__ float sigmoid_f(float v) {
    return __fdividef(1.0f, 1.0f + __expf(-v));
}
__device__ __forceinline__ float tanh_f(float v) {
    return 1.0f - __fdividef(2.0f, __expf(2.0f * v) + 1.0f);
}

// ---------------------------------------------------------------------------
// Recurrent kernel. CTA = 32 batch rows, 8 warps, 30 steps.
// A fragments (bf16 hi/lo) double-buffered in smem: [buf][ktile 0..9][mtile][lane].
// ktiles 0-1 = x_t (fed back y), ktiles 2-9 = h_t. Warp w: gate cols [16w,16w+16).
// ---------------------------------------------------------------------------
__global__ __launch_bounds__(NTH, 2)
void gru_kernel(const float* __restrict__ x,
                const float* __restrict__ h0,
                const float* __restrict__ b_out,
                float* __restrict__ out)
{
    __shared__ uint4 sAh[2][10][2][32];   // 20 KB  (bf16-hi A fragments)
    __shared__ uint4 sAl[2][10][2][32];   // 20 KB  (bf16-lo residuals)

    const int tid = threadIdx.x;
    const int w   = tid >> 5;          // warp 0..7
    const int l   = tid & 31;          // lane
    const int b0  = blockIdx.x * MT;
    const int r4  = l >> 2;            // fragment row (0..7)
    const int c2  = (l & 3) * 2;       // fragment col pair base

    // ---- prologue: build A fragments for t=0 (x0 = x[:,30,:], h = h0) ----
    for (int kt = w; kt < 10; kt += NWARP) {
#pragma unroll
        for (int mt = 0; mt < 2; mt++) {
            float e[8];   // a0:{e0,e1} a1:{e2,e3} a2:{e4,e5} a3:{e6,e7}
#pragma unroll
            for (int q = 0; q < 4; q++) {
                int row = b0 + mt * 16 + r4 + 8 * (q & 1);
                int k   = kt * 16 + c2 + 8 * (q >> 1);
                float2 v;
                if (k < 32)
                    v = *(const float2*)&x[(size_t)row * (TT * II) + SEQOFF * II + k];
                else
                    v = *(const float2*)&h0[(size_t)row * HH + (k - 32)];
                e[2 * q] = v.x; e[2 * q + 1] = v.y;
            }
            u32 lo0, lo1, lo2, lo3;
            u32 hi0 = packhl(e[0], e[1], lo0);
            u32 hi1 = packhl(e[2], e[3], lo1);
            u32 hi2 = packhl(e[4], e[5], lo2);
            u32 hi3 = packhl(e[6], e[7], lo3);
            sAh[0][kt][mt][l] = make_uint4(hi0, hi1, hi2, hi3);
            sAl[0][kt][mt][l] = make_uint4(lo0, lo1, lo2, lo3);
        }
    }

    // ---- persistent fp32 hidden state for this warp's 16 cols ----
    // hOld[mt][nt2][e]: row = mt*16 + r4 + 8*(e>>1), col = 16w + 8*nt2 + c2 + (e&1)
    float hOld[2][2][4];
#pragma unroll
    for (int mt = 0; mt < 2; mt++)
#pragma unroll
        for (int nt2 = 0; nt2 < 2; nt2++)
#pragma unroll
            for (int rh = 0; rh < 2; rh++) {
                int row = b0 + mt * 16 + r4 + 8 * rh;
                int col = 16 * w + 8 * nt2 + c2;
                float2 v = *(const float2*)&h0[(size_t)row * HH + col];
                hOld[mt][nt2][2 * rh]     = v.x;
                hOld[mt][nt2][2 * rh + 1] = v.y;
            }

    const int mty = w >> 2, nty = w & 3;   // this warp's y-output tile
    const float2 bo2 = *(const float2*)&b_out[nty * 8 + c2];
    __syncthreads();

    for (int t = 0; t < STEPS; t++) {
        const int cur = t & 1, nxt = cur ^ 1;

        float aR[2][2][4], aZ[2][2][4], aIN[2][2][4], aHN[2][2][4];
#pragma unroll
        for (int mt = 0; mt < 2; mt++)
#pragma unroll
            for (int nt2 = 0; nt2 < 2; nt2++)
#pragma unroll
                for (int e = 0; e < 4; e++) {
                    aR[mt][nt2][e] = 0.f; aZ[mt][nt2][e] = 0.f;
                    aIN[mt][nt2][e] = 0.f; aHN[mt][nt2][e] = 0.f;
                }

#define KT_BODY(KT, NACC)                                                         \
        {                                                                         \
            const uint4 A0h = sAh[cur][KT][0][l];                                 \
            const uint4 A0l = sAl[cur][KT][0][l];                                 \
            const uint4 A1h = sAh[cur][KT][1][l];                                 \
            const uint4 A1l = sAl[cur][KT][1][l];                                 \
            const int gb = ((w * 10 + (KT)) * 6) * 32 + l;                        \
            mma_pair(aR[0][0], aR[1][0], A0h,A0l,A1h,A1l, __ldg(&g_B[gb]));       \
            mma_pair(aR[0][1], aR[1][1], A0h,A0l,A1h,A1l, __ldg(&g_B[gb+32]));    \
            mma_pair(aZ[0][0], aZ[1][0], A0h,A0l,A1h,A1l, __ldg(&g_B[gb+64]));    \
            mma_pair(aZ[0][1], aZ[1][1], A0h,A0l,A1h,A1l, __ldg(&g_B[gb+96]));    \
            mma_pair(NACC[0][0], NACC[1][0], A0h,A0l,A1h,A1l, __ldg(&g_B[gb+128]));\
            mma_pair(NACC[0][1], NACC[1][1], A0h,A0l,A1h,A1l, __ldg(&g_B[gb+160]));\
        }

        KT_BODY(0, aIN)  KT_BODY(1, aIN)
        KT_BODY(2, aHN)  KT_BODY(3, aHN)  KT_BODY(4, aHN)  KT_BODY(5, aHN)
        KT_BODY(6, aHN)  KT_BODY(7, aHN)  KT_BODY(8, aHN)  KT_BODY(9, aHN)
#undef KT_BODY

        // ---- epilogue: gates -> h_new (fp32 state), write A frags ktile 2+w ----
        float hn[2][2][4];   // [mt][nt2][e]
#pragma unroll
        for (int nt2 = 0; nt2 < 2; nt2++) {
            const int cb = 16 * w + 8 * nt2 + c2;
            const float2 brv = *(const float2*)&g_br[cb];
            const float2 bzv = *(const float2*)&g_bz[cb];
            const float2 biv = *(const float2*)&g_bin[cb];
            const float2 bhv = *(const float2*)&g_bhn[cb];
#pragma unroll
            for (int mt = 0; mt < 2; mt++)
#pragma unroll
                for (int e = 0; e < 4; e++) {
                    const float bR = (e & 1) ? brv.y : brv.x;
                    const float bZ = (e & 1) ? bzv.y : bzv.x;
                    const float bI = (e & 1) ? biv.y : biv.x;
                    const float bH = (e & 1) ? bhv.y : bhv.x;
                    float r = sigmoid_f(aR[mt][nt2][e] + bR);
                    float z = sigmoid_f(aZ[mt][nt2][e] + bZ);
                    float n = tanh_f(fmaf(r, aHN[mt][nt2][e] + bH,
                                          aIN[mt][nt2][e] + bI));
                    float hv = n + z * (hOld[mt][nt2][e] - n);
                    hOld[mt][nt2][e] = hv;
                    hn[mt][nt2][e] = hv;
                }
        }
#pragma unroll
        for (int mt = 0; mt < 2; mt++) {
            u32 lo0, lo1, lo2, lo3;
            u32 hi0 = packhl(hn[mt][0][0], hn[mt][0][1], lo0);
            u32 hi1 = packhl(hn[mt][0][2], hn[mt][0][3], lo1);
            u32 hi2 = packhl(hn[mt][1][0], hn[mt][1][1], lo2);
            u32 hi3 = packhl(hn[mt][1][2], hn[mt][1][3], lo3);
            sAh[nxt][2 + w][mt][l] = make_uint4(hi0, hi1, hi2, hi3);
            sAl[nxt][2 + w][mt][l] = make_uint4(lo0, lo1, lo2, lo3);
        }
        __syncthreads();   // all h_new fragments visible

        // ---- y = h_new @ W_out^T + b_out : warp w owns (mty, nty) D tile ----
        float y[4] = {bo2.x, bo2.y, bo2.x, bo2.y};
#pragma unroll
        for (int kt = 0; kt < 8; kt++) {
            const uint4 Ah = sAh[nxt][2 + kt][mty][l];
            const uint4 Al = sAl[nxt][2 + kt][mty][l];
            const uint4 wf = __ldg(&g_Wo[(kt * 4 + nty) * 32 + l]);
            mma_bf16(y, Ah, wf.x, wf.y);
            mma_bf16(y, Al, wf.x, wf.y);
            mma_bf16(y, Ah, wf.z, wf.w);
        }

        // global output
        {
            const size_t row0 = (size_t)b0 + mty * 16 + r4;
            const int col = nty * 8 + c2;
            *(float2*)&out[(row0 * STEPS + t) * II + col]       = make_float2(y[0], y[1]);
            *(float2*)&out[((row0 + 8) * STEPS + t) * II + col] = make_float2(y[2], y[3]);
        }

        // y feeds back as x_{t+1}: half of A-frag ktile nty>>1, mtile mty
        {
            u32 flo0, flo1;
            u32 fhi0 = packhl(y[0], y[1], flo0);
            u32 fhi1 = packhl(y[2], y[3], flo1);
            const int ktx = nty >> 1, half = nty & 1;
            u32* ph = (u32*)&sAh[nxt][ktx][mty][l];
            u32* pl = (u32*)&sAl[nxt][ktx][mty][l];
            ph[2 * half]     = fhi0;
            ph[2 * half + 1] = fhi1;
            pl[2 * half]     = flo0;
            pl[2 * half + 1] = flo1;
        }
        __syncthreads();   // buffer nxt complete before next step reads it
    }
}

// ---------------------------------------------------------------------------
// Harness entry point
// ---------------------------------------------------------------------------
extern "C" void kernel_launch(void* const* d_in, const int* in_sizes, int n_in,
                              void* d_out, int out_size)
{
    const float* x     = (const float*)d_in[0];
    const float* h     = (const float*)d_in[1];
    const float* W_ih  = (const float*)d_in[2];
    const float* W_hh  = (const float*)d_in[3];
    const float* b_ih  = (const float*)d_in[4];
    const float* b_hh  = (const float*)d_in[5];
    const float* W_out = (const float*)d_in[6];
    const float* b_out = (const float*)d_in[7];
    float* out = (float*)d_out;

    pack_kernel<<<65, 256>>>(W_ih, W_hh, W_out, b_ih, b_hh);
    gru_kernel<<<BB / MT, NTH>>>(x, h, b_out, out);
}

// round 13
// speedup vs baseline: 5.1536x; 1.3019x over previous
#include <cuda_runtime.h>
#include <cuda_fp16.h>

// Problem constants
#define BB     16384
#define TT     60
#define II     32
#define HH     128
#define STEPS  30
#define SEQOFF 30

#define MT    32       // batch rows per CTA (2 m16 tiles)
#define NTH   256
#define NWARP 8

typedef unsigned int u32;

// ---------------------------------------------------------------------------
// Fragment-packed weights (uint4 = {wh_k0, wh_k1, wl_k0, wl_k1} fp16x2 per lane).
// wh = fp16(w), wl = fp16(w - wh)  (residual lands in fp16 subnormal range ->
// the hi/lo pair is effectively exact; only activations carry rounding error).
// Gate B matrix: B[k][col], k in [0,160) (0-31 = x-part, 32-159 = h-part),
// col = gate*128 + j with gate 0=r,1=z,2=n.
// g_B[((w*10 + kt)*6 + tau)*32 + lane]; tau: 0,1=r 2,3=z 4,5=n; nt2 = tau&1.
// g_Wo[(kt*4 + nt)*32 + lane] for y = h @ W_out^T (B[k][i] = W_out[i][k]).
// ---------------------------------------------------------------------------
__device__ uint4 g_B[15360];
__device__ uint4 g_Wo[1024];
__device__ float g_br[128], g_bz[128], g_bin[128], g_bhn[128];

__device__ __forceinline__ u32 f2h2(float a, float b) {
    __half2 h = __floats2half2_rn(a, b);   // a -> low, b -> high
    return *(u32*)&h;
}
__device__ __forceinline__ void packw(float a, float b, u32& hi, u32& lo) {
    __half ha = __float2half_rn(a), hb = __float2half_rn(b);
    hi = ((u32)__half_as_ushort(hb) << 16) | (u32)__half_as_ushort(ha);
    lo = f2h2(a - __half2float(ha), b - __half2float(hb));
}

__global__ void pack_kernel(const float* __restrict__ W_ih,
                            const float* __restrict__ W_hh,
                            const float* __restrict__ W_out,
                            const float* __restrict__ b_ih,
                            const float* __restrict__ b_hh)
{
    int idx = blockIdx.x * blockDim.x + threadIdx.x;
    if (idx < 15360) {                       // gate weight fragments
        int lane = idx & 31, tau = (idx >> 5) % 6, kt = (idx / 192) % 10, w = idx / 1920;
        int gate = tau >> 1, nt2 = tau & 1;
        int n = lane >> 2, tg = lane & 3;
        int col = gate * 128 + 16 * w + 8 * nt2 + n;
        float e[4];
#pragma unroll
        for (int q = 0; q < 4; q++) {
            int k = kt * 16 + 2 * tg + (q & 1) + 8 * (q >> 1);
            e[q] = (k < 32) ? W_ih[col * 32 + k] : W_hh[col * 128 + (k - 32)];
        }
        u32 hi0, hi1, lo0, lo1;
        packw(e[0], e[1], hi0, lo0);
        packw(e[2], e[3], hi1, lo1);
        g_B[idx] = make_uint4(hi0, hi1, lo0, lo1);
    }
    int i2 = idx - 15360;
    if (i2 >= 0 && i2 < 1024) {              // W_out fragments
        int lane = i2 & 31, nt = (i2 >> 5) & 3, kt = i2 >> 7;
        int i = nt * 8 + (lane >> 2), tg = lane & 3;
        float e[4];
#pragma unroll
        for (int q = 0; q < 4; q++) {
            int k = kt * 16 + 2 * tg + (q & 1) + 8 * (q >> 1);
            e[q] = W_out[i * 128 + k];
        }
        u32 hi0, hi1, lo0, lo1;
        packw(e[0], e[1], hi0, lo0);
        packw(e[2], e[3], hi1, lo1);
        g_Wo[i2] = make_uint4(hi0, hi1, lo0, lo1);
    }
    int i4 = idx - 16384;
    if (i4 >= 0 && i4 < 128) {
        g_br[i4]  = b_ih[i4]       + b_hh[i4];
        g_bz[i4]  = b_ih[128 + i4] + b_hh[128 + i4];
        g_bin[i4] = b_ih[256 + i4];
        g_bhn[i4] = b_hh[256 + i4];
    }
}

__device__ __forceinline__ void mma_f16(float (&d)[4], const uint4& a, u32 b0, u32 b1) {
    asm("mma.sync.aligned.m16n8k16.row.col.f32.f16.f16.f32 "
        "{%0,%1,%2,%3},{%4,%5,%6,%7},{%8,%9},{%0,%1,%2,%3};"
        : "+f"(d[0]), "+f"(d[1]), "+f"(d[2]), "+f"(d[3])
        : "r"(a.x), "r"(a.y), "r"(a.z), "r"(a.w), "r"(b0), "r"(b1));
}

// 2-pass (Wh + Wl) MMA into two m-tiles' accumulators with one weight fragment
__device__ __forceinline__ void mma_pair(float (&d0)[4], float (&d1)[4],
                                         const uint4& A0, const uint4& A1,
                                         const uint4& wf) {
    mma_f16(d0, A0, wf.x, wf.y);
    mma_f16(d0, A0, wf.z, wf.w);
    mma_f16(d1, A1, wf.x, wf.y);
    mma_f16(d1, A1, wf.z, wf.w);
}

__device__ __forceinline__ float sigmoid_f(float v) {
    return __fdividef(1.0f, 1.0f + __expf(-v));
}
__device__ __forceinline__ float tanh_f(float v) {
    return 1.0f - __fdividef(2.0f, __expf(2.0f * v) + 1.0f);
}

// ---------------------------------------------------------------------------
// Recurrent kernel. CTA = 32 batch rows, 8 warps, 30 steps.
// A fragments (fp16) double-buffered in smem: [buf][ktile 0..9][mtile][lane].
// ktiles 0-1 = x_t (fed back y), ktiles 2-9 = h_t. Warp w: gate cols [16w,16w+16).
// h state kept exact fp32 in registers (warp-owned), so no recurrence drift.
// ---------------------------------------------------------------------------
__global__ __launch_bounds__(NTH, 2)
void gru_kernel(const float* __restrict__ x,
                const float* __restrict__ h0,
                const float* __restrict__ b_out,
                float* __restrict__ out)
{
    __shared__ uint4 sA[2][10][2][32];   // 20 KB (fp16 A fragments)

    const int tid = threadIdx.x;
    const int w   = tid >> 5;
    const int l   = tid & 31;
    const int b0  = blockIdx.x * MT;
    const int r4  = l >> 2;            // fragment row (0..7)
    const int c2  = (l & 3) * 2;       // fragment col pair base

    // ---- prologue: build A fragments for t=0 (x0 = x[:,30,:], h = h0) ----
    for (int kt = w; kt < 10; kt += NWARP) {
#pragma unroll
        for (int mt = 0; mt < 2; mt++) {
            float e[8];
#pragma unroll
            for (int q = 0; q < 4; q++) {
                int row = b0 + mt * 16 + r4 + 8 * (q & 1);
                int k   = kt * 16 + c2 + 8 * (q >> 1);
                float2 v;
                if (k < 32)
                    v = *(const float2*)&x[(size_t)row * (TT * II) + SEQOFF * II + k];
                else
                    v = *(const float2*)&h0[(size_t)row * HH + (k - 32)];
                e[2 * q] = v.x; e[2 * q + 1] = v.y;
            }
            sA[0][kt][mt][l] = make_uint4(f2h2(e[0], e[1]), f2h2(e[2], e[3]),
                                          f2h2(e[4], e[5]), f2h2(e[6], e[7]));
        }
    }

    // ---- persistent fp32 hidden state for this warp's 16 cols ----
    float hOld[2][2][4];
#pragma unroll
    for (int mt = 0; mt < 2; mt++)
#pragma unroll
        for (int nt2 = 0; nt2 < 2; nt2++)
#pragma unroll
            for (int rh = 0; rh < 2; rh++) {
                int row = b0 + mt * 16 + r4 + 8 * rh;
                int col = 16 * w + 8 * nt2 + c2;
                float2 v = *(const float2*)&h0[(size_t)row * HH + col];
                hOld[mt][nt2][2 * rh]     = v.x;
                hOld[mt][nt2][2 * rh + 1] = v.y;
            }

    const int mty = w >> 2, nty = w & 3;   // this warp's y-output tile
    const float2 bo2 = *(const float2*)&b_out[nty * 8 + c2];
    __syncthreads();

    for (int t = 0; t < STEPS; t++) {
        const int cur = t & 1, nxt = cur ^ 1;

        float aR[2][2][4], aZ[2][2][4], aIN[2][2][4], aHN[2][2][4];
#pragma unroll
        for (int mt = 0; mt < 2; mt++)
#pragma unroll
            for (int nt2 = 0; nt2 < 2; nt2++)
#pragma unroll
                for (int e = 0; e < 4; e++) {
                    aR[mt][nt2][e] = 0.f; aZ[mt][nt2][e] = 0.f;
                    aIN[mt][nt2][e] = 0.f; aHN[mt][nt2][e] = 0.f;
                }

#define KT_BODY(KT, NACC)                                                         \
        {                                                                         \
            const uint4 A0 = sA[cur][KT][0][l];                                   \
            const uint4 A1 = sA[cur][KT][1][l];                                   \
            const int gb = ((w * 10 + (KT)) * 6) * 32 + l;                        \
            mma_pair(aR[0][0], aR[1][0], A0, A1, __ldg(&g_B[gb]));                \
            mma_pair(aR[0][1], aR[1][1], A0, A1, __ldg(&g_B[gb+32]));             \
            mma_pair(aZ[0][0], aZ[1][0], A0, A1, __ldg(&g_B[gb+64]));             \
            mma_pair(aZ[0][1], aZ[1][1], A0, A1, __ldg(&g_B[gb+96]));             \
            mma_pair(NACC[0][0], NACC[1][0], A0, A1, __ldg(&g_B[gb+128]));        \
            mma_pair(NACC[0][1], NACC[1][1], A0, A1, __ldg(&g_B[gb+160]));        \
        }

        KT_BODY(0, aIN)  KT_BODY(1, aIN)
        KT_BODY(2, aHN)  KT_BODY(3, aHN)  KT_BODY(4, aHN)  KT_BODY(5, aHN)
        KT_BODY(6, aHN)  KT_BODY(7, aHN)  KT_BODY(8, aHN)  KT_BODY(9, aHN)
#undef KT_BODY

        // ---- epilogue: gates -> h_new (fp32 state), write A frag ktile 2+w ----
        float hn[2][2][4];
#pragma unroll
        for (int nt2 = 0; nt2 < 2; nt2++) {
            const int cb = 16 * w + 8 * nt2 + c2;
            const float2 brv = *(const float2*)&g_br[cb];
            const float2 bzv = *(const float2*)&g_bz[cb];
            const float2 biv = *(const float2*)&g_bin[cb];
            const float2 bhv = *(const float2*)&g_bhn[cb];
#pragma unroll
            for (int mt = 0; mt < 2; mt++)
#pragma unroll
                for (int e = 0; e < 4; e++) {
                    const float bR = (e & 1) ? brv.y : brv.x;
                    const float bZ = (e & 1) ? bzv.y : bzv.x;
                    const float bI = (e & 1) ? biv.y : biv.x;
                    const float bH = (e & 1) ? bhv.y : bhv.x;
                    float r = sigmoid_f(aR[mt][nt2][e] + bR);
                    float z = sigmoid_f(aZ[mt][nt2][e] + bZ);
                    float n = tanh_f(fmaf(r, aHN[mt][nt2][e] + bH,
                                          aIN[mt][nt2][e] + bI));
                    float hv = n + z * (hOld[mt][nt2][e] - n);
                    hOld[mt][nt2][e] = hv;
                    hn[mt][nt2][e] = hv;
                }
        }
#pragma unroll
        for (int mt = 0; mt < 2; mt++) {
            sA[nxt][2 + w][mt][l] = make_uint4(
                f2h2(hn[mt][0][0], hn[mt][0][1]),
                f2h2(hn[mt][0][2], hn[mt][0][3]),
                f2h2(hn[mt][1][0], hn[mt][1][1]),
                f2h2(hn[mt][1][2], hn[mt][1][3]));
        }
        __syncthreads();   // all h_new fragments visible

        // ---- y = h_new @ W_out^T + b_out : warp w owns (mty, nty) D tile ----
        float y[4] = {bo2.x, bo2.y, bo2.x, bo2.y};
#pragma unroll
        for (int kt = 0; kt < 8; kt++) {
            const uint4 Ah = sA[nxt][2 + kt][mty][l];
            const uint4 wf = __ldg(&g_Wo[(kt * 4 + nty) * 32 + l]);
            mma_f16(y, Ah, wf.x, wf.y);
            mma_f16(y, Ah, wf.z, wf.w);
        }

        // global output
        {
            const size_t row0 = (size_t)b0 + mty * 16 + r4;
            const int col = nty * 8 + c2;
            *(float2*)&out[(row0 * STEPS + t) * II + col]       = make_float2(y[0], y[1]);
            *(float2*)&out[((row0 + 8) * STEPS + t) * II + col] = make_float2(y[2], y[3]);
        }

        // y feeds back as x_{t+1}: half of A-frag ktile nty>>1, mtile mty
        {
            const int ktx = nty >> 1, half = nty & 1;
            u32* ph = (u32*)&sA[nxt][ktx][mty][l];
            ph[2 * half]     = f2h2(y[0], y[1]);
            ph[2 * half + 1] = f2h2(y[2], y[3]);
        }
        __syncthreads();   // buffer nxt complete before next step reads it
    }
}

// ---------------------------------------------------------------------------
// Harness entry point
// ---------------------------------------------------------------------------
extern "C" void kernel_launch(void* const* d_in, const int* in_sizes, int n_in,
                              void* d_out, int out_size)
{
    const float* x     = (const float*)d_in[0];
    const float* h     = (const float*)d_in[1];
    const float* W_ih  = (const float*)d_in[2];
    const float* W_hh  = (const float*)d_in[3];
    const float* b_ih  = (const float*)d_in[4];
    const float* b_hh  = (const float*)d_in[5];
    const float* W_out = (const float*)d_in[6];
    const float* b_out = (const float*)d_in[7];
    float* out = (float*)d_out;

    pack_kernel<<<65, 256>>>(W_ih, W_hh, W_out, b_ih, b_hh);
    gru_kernel<<<BB / MT, NTH>>>(x, h, b_out, out);
}

// round 15
// speedup vs baseline: 6.4347x; 1.2486x over previous
#include <cuda_runtime.h>
#include <cuda_fp16.h>

// Problem constants
#define BB     16384
#define TT     60
#define II     32
#define HH     128
#define STEPS  30
#define SEQOFF 30

#define MT    32       // batch rows per CTA (2 m16 tiles)
#define NTH   256
#define NWARP 8

typedef unsigned int u32;

// ---------------------------------------------------------------------------
// Weight folding: for t>=1, x_t = y_{t-1} = h·Wo^T + bo, so gate pre-acts are
// pure functions of h:  Wcomb = W_ih @ W_out  [384x128],
//   r/z:  single merged matrix (W_hh + Wcomb), 1-pass fp16 (hi only)
//   n  :  aIN via Wcomb_n (2-pass hi/lo), aHN via W_hh_n (2-pass hi/lo)
// Step 0 uses the original K=160 path (real x) with g_B (R13 layout).
// ---------------------------------------------------------------------------
__device__ float g_Wcomb[384 * 128];
__device__ float g_bxo[384];

__device__ uint4 g_B[15360];    // t=0 weights: [(w*10+kt)*6+tau]*32+lane (hi,hi,lo,lo)
__device__ uint2 g_Brz[8192];   // t>=1 merged r/z: [(w*8+kt)*4+tau]*32+lane (hi only)
__device__ uint4 g_Bn[8192];    // t>=1 n: tau 0,1=in(Wcomb_n) 2,3=hn(W_hh_n), hi/lo
__device__ uint4 g_Wo[1024];    // y weights: [(kt*4+nt)*32+lane], hi/lo
__device__ float g_br0[128], g_bz0[128], g_bin0[128];   // t=0 biases
__device__ float g_br1[128], g_bz1[128], g_bin1[128];   // t>=1 (Wx·bo folded)
__device__ float g_bhn[128];

__device__ __forceinline__ u32 f2h2(float a, float b) {
    __half2 h = __floats2half2_rn(a, b);   // a -> low, b -> high
    return *(u32*)&h;
}
__device__ __forceinline__ void packw(float a, float b, u32& hi, u32& lo) {
    __half ha = __float2half_rn(a), hb = __float2half_rn(b);
    hi = ((u32)__half_as_ushort(hb) << 16) | (u32)__half_as_ushort(ha);
    lo = f2h2(a - __half2float(ha), b - __half2float(hb));
}

// pack stage 1: Wcomb = W_ih @ W_out, bxo = W_ih @ b_out
__global__ void pack1(const float* __restrict__ W_ih,
                      const float* __restrict__ W_out,
                      const float* __restrict__ b_out)
{
    int idx = blockIdx.x * blockDim.x + threadIdx.x;
    if (idx < 384 * 128) {
        int col = idx >> 7, j = idx & 127;
        float s = 0.f;
#pragma unroll
        for (int i = 0; i < 32; i++)
            s += W_ih[col * 32 + i] * W_out[i * 128 + j];
        g_Wcomb[idx] = s;
    }
    int i2 = idx - 49152;
    if (i2 >= 0 && i2 < 384) {
        float s = 0.f;
#pragma unroll
        for (int i = 0; i < 32; i++)
            s += W_ih[i2 * 32 + i] * b_out[i];
        g_bxo[i2] = s;
    }
}

// pack stage 2: all fragment-packed weight arrays + biases
__global__ void pack2(const float* __restrict__ W_ih,
                      const float* __restrict__ W_hh,
                      const float* __restrict__ W_out,
                      const float* __restrict__ b_ih,
                      const float* __restrict__ b_hh)
{
    int idx = blockIdx.x * blockDim.x + threadIdx.x;
    if (idx < 15360) {                       // t=0 gate fragments (K=160, R13 layout)
        int lane = idx & 31, tau = (idx >> 5) % 6, kt = (idx / 192) % 10, w = idx / 1920;
        int gate = tau >> 1, nt2 = tau & 1;
        int n = lane >> 2, tg = lane & 3;
        int col = gate * 128 + 16 * w + 8 * nt2 + n;
        float e[4];
#pragma unroll
        for (int q = 0; q < 4; q++) {
            int k = kt * 16 + 2 * tg + (q & 1) + 8 * (q >> 1);
            e[q] = (k < 32) ? W_ih[col * 32 + k] : W_hh[col * 128 + (k - 32)];
        }
        u32 hi0, hi1, lo0, lo1;
        packw(e[0], e[1], hi0, lo0);
        packw(e[2], e[3], hi1, lo1);
        g_B[idx] = make_uint4(hi0, hi1, lo0, lo1);
    }
    int ib = idx - 15360;
    if (ib >= 0 && ib < 8192) {              // merged r/z fragments (hi only)
        int lane = ib & 31, tau = (ib >> 5) & 3, kt = (ib >> 7) & 7, w = ib >> 10;
        int gate = tau >> 1, nt2 = tau & 1;
        int n = lane >> 2, tg = lane & 3;
        int col = gate * 128 + 16 * w + 8 * nt2 + n;
        float e[4];
#pragma unroll
        for (int q = 0; q < 4; q++) {
            int k = kt * 16 + 2 * tg + (q & 1) + 8 * (q >> 1);
            e[q] = W_hh[col * 128 + k] + g_Wcomb[col * 128 + k];
        }
        g_Brz[ib] = make_uint2(f2h2(e[0], e[1]), f2h2(e[2], e[3]));
    }
    int in_ = idx - 23552;
    if (in_ >= 0 && in_ < 8192) {            // n fragments (hi/lo)
        int lane = in_ & 31, tau = (in_ >> 5) & 3, kt = (in_ >> 7) & 7, w = in_ >> 10;
        int isIn = (tau < 2), nt2 = tau & 1;
        int n = lane >> 2, tg = lane & 3;
        int col = 256 + 16 * w + 8 * nt2 + n;
        float e[4];
#pragma unroll
        for (int q = 0; q < 4; q++) {
            int k = kt * 16 + 2 * tg + (q & 1) + 8 * (q >> 1);
            e[q] = isIn ? g_Wcomb[col * 128 + k] : W_hh[col * 128 + k];
        }
        u32 hi0, hi1, lo0, lo1;
        packw(e[0], e[1], hi0, lo0);
        packw(e[2], e[3], hi1, lo1);
        g_Bn[in_] = make_uint4(hi0, hi1, lo0, lo1);
    }
    int iw = idx - 31744;
    if (iw >= 0 && iw < 1024) {              // W_out fragments
        int lane = iw & 31, nt = (iw >> 5) & 3, kt = iw >> 7;
        int i = nt * 8 + (lane >> 2), tg = lane & 3;
        float e[4];
#pragma unroll
        for (int q = 0; q < 4; q++) {
            int k = kt * 16 + 2 * tg + (q & 1) + 8 * (q >> 1);
            e[q] = W_out[i * 128 + k];
        }
        u32 hi0, hi1, lo0, lo1;
        packw(e[0], e[1], hi0, lo0);
        packw(e[2], e[3], hi1, lo1);
        g_Wo[iw] = make_uint4(hi0, hi1, lo0, lo1);
    }
    int i4 = idx - 32768;
    if (i4 >= 0 && i4 < 128) {               // biases
        float br = b_ih[i4]       + b_hh[i4];
        float bz = b_ih[128 + i4] + b_hh[128 + i4];
        float bi = b_ih[256 + i4];
        g_br0[i4]  = br;  g_br1[i4]  = br + g_bxo[i4];
        g_bz0[i4]  = bz;  g_bz1[i4]  = bz + g_bxo[128 + i4];
        g_bin0[i4] = bi;  g_bin1[i4] = bi + g_bxo[256 + i4];
        g_bhn[i4]  = b_hh[256 + i4];
    }
}

__device__ __forceinline__ void mma_f16(float (&d)[4], const uint4& a, u32 b0, u32 b1) {
    asm("mma.sync.aligned.m16n8k16.row.col.f32.f16.f16.f32 "
        "{%0,%1,%2,%3},{%4,%5,%6,%7},{%8,%9},{%0,%1,%2,%3};"
        : "+f"(d[0]), "+f"(d[1]), "+f"(d[2]), "+f"(d[3])
        : "r"(a.x), "r"(a.y), "r"(a.z), "r"(a.w), "r"(b0), "r"(b1));
}

// 2-pass (Wh + Wl) MMA into two m-tiles' accumulators
__device__ __forceinline__ void mma_pair(float (&d0)[4], float (&d1)[4],
                                         const uint4& A0, const uint4& A1,
                                         const uint4& wf) {
    mma_f16(d0, A0, wf.x, wf.y);
    mma_f16(d0, A0, wf.z, wf.w);
    mma_f16(d1, A1, wf.x, wf.y);
    mma_f16(d1, A1, wf.z, wf.w);
}

__device__ __forceinline__ float sigmoid_f(float v) {
    return __fdividef(1.0f, 1.0f + __expf(-v));
}
__device__ __forceinline__ float tanh_f(float v) {
    return 1.0f - __fdividef(2.0f, __expf(2.0f * v) + 1.0f);
}

// ---------------------------------------------------------------------------
// Recurrent kernel. CTA = 32 batch rows, 8 warps, 30 steps, ONE barrier/step.
// sA: h fragments (fp16), double-buffered, 8 ktiles (K=128). Warp w owns gate
// cols [16w,16w+16) == h ktile w. y-GEMM is off the recurrence critical path.
// ---------------------------------------------------------------------------
__global__ __launch_bounds__(NTH, 2)
void gru_kernel(const float* __restrict__ x,
                const float* __restrict__ h0,
                const float* __restrict__ b_out,
                float* __restrict__ out)
{
    __shared__ uint4 sA[2][8][2][32];   // 16 KB
    __shared__ uint4 sX[2][2][32];      // 2 KB  (x0 fragments, t=0 only)

    const int tid = threadIdx.x;
    const int w   = tid >> 5;
    const int l   = tid & 31;
    const int b0  = blockIdx.x * MT;
    const int r4  = l >> 2;
    const int c2  = (l & 3) * 2;

    // ---- prologue: h0 fragments (warp w -> ktile w) ----
#pragma unroll
    for (int mt = 0; mt < 2; mt++) {
        float e[8];
#pragma unroll
        for (int q = 0; q < 4; q++) {
            int row = b0 + mt * 16 + r4 + 8 * (q & 1);
            int k   = w * 16 + c2 + 8 * (q >> 1);
            float2 v = *(const float2*)&h0[(size_t)row * HH + k];
            e[2 * q] = v.x; e[2 * q + 1] = v.y;
        }
        sA[0][w][mt][l] = make_uint4(f2h2(e[0], e[1]), f2h2(e[2], e[3]),
                                     f2h2(e[4], e[5]), f2h2(e[6], e[7]));
    }
    // x0 fragments: warps 0-3 -> (kt = w>>1, mt = w&1)
    if (w < 4) {
        const int kt = w >> 1, mt = w & 1;
        float e[8];
#pragma unroll
        for (int q = 0; q < 4; q++) {
            int row = b0 + mt * 16 + r4 + 8 * (q & 1);
            int k   = kt * 16 + c2 + 8 * (q >> 1);
            float2 v = *(const float2*)&x[(size_t)row * (TT * II) + SEQOFF * II + k];
            e[2 * q] = v.x; e[2 * q + 1] = v.y;
        }
        sX[kt][mt][l] = make_uint4(f2h2(e[0], e[1]), f2h2(e[2], e[3]),
                                   f2h2(e[4], e[5]), f2h2(e[6], e[7]));
    }

    // ---- persistent fp32 hidden state for this warp's 16 cols ----
    float hOld[2][2][4];
#pragma unroll
    for (int mt = 0; mt < 2; mt++)
#pragma unroll
        for (int nt2 = 0; nt2 < 2; nt2++)
#pragma unroll
            for (int rh = 0; rh < 2; rh++) {
                int row = b0 + mt * 16 + r4 + 8 * rh;
                int col = 16 * w + 8 * nt2 + c2;
                float2 v = *(const float2*)&h0[(size_t)row * HH + col];
                hOld[mt][nt2][2 * rh]     = v.x;
                hOld[mt][nt2][2 * rh + 1] = v.y;
            }

    const int mty = w >> 2, nty = w & 3;   // this warp's y-output tile
    const float2 bo2 = *(const float2*)&b_out[nty * 8 + c2];
    __syncthreads();

    for (int t = 0; t < STEPS; t++) {
        const int cur = t & 1, nxt = cur ^ 1;

        float aR[2][2][4], aZ[2][2][4], aIN[2][2][4], aHN[2][2][4];
#pragma unroll
        for (int mt = 0; mt < 2; mt++)
#pragma unroll
            for (int nt2 = 0; nt2 < 2; nt2++)
#pragma unroll
                for (int e = 0; e < 4; e++) {
                    aR[mt][nt2][e] = 0.f; aZ[mt][nt2][e] = 0.f;
                    aIN[mt][nt2][e] = 0.f; aHN[mt][nt2][e] = 0.f;
                }

        if (t == 0) {
            // original K=160 path (real x), 2-pass everywhere
#pragma unroll
            for (int kt = 0; kt < 10; kt++) {
                uint4 A0, A1;
                if (kt < 2) { A0 = sX[kt][0][l];     A1 = sX[kt][1][l]; }
                else        { A0 = sA[0][kt - 2][0][l]; A1 = sA[0][kt - 2][1][l]; }
                const int gb = ((w * 10 + kt) * 6) * 32 + l;
                mma_pair(aR[0][0], aR[1][0], A0, A1, __ldg(&g_B[gb]));
                mma_pair(aR[0][1], aR[1][1], A0, A1, __ldg(&g_B[gb + 32]));
                mma_pair(aZ[0][0], aZ[1][0], A0, A1, __ldg(&g_B[gb + 64]));
                mma_pair(aZ[0][1], aZ[1][1], A0, A1, __ldg(&g_B[gb + 96]));
                if (kt < 2) {
                    mma_pair(aIN[0][0], aIN[1][0], A0, A1, __ldg(&g_B[gb + 128]));
                    mma_pair(aIN[0][1], aIN[1][1], A0, A1, __ldg(&g_B[gb + 160]));
                } else {
                    mma_pair(aHN[0][0], aHN[1][0], A0, A1, __ldg(&g_B[gb + 128]));
                    mma_pair(aHN[0][1], aHN[1][1], A0, A1, __ldg(&g_B[gb + 160]));
                }
            }
        } else {
            // merged K=128 path: r/z 1-pass, n 2-pass
#define KT1(KT)                                                                   \
            {                                                                     \
                const uint4 A0 = sA[cur][KT][0][l];                               \
                const uint4 A1 = sA[cur][KT][1][l];                               \
                const int rb = ((w * 8 + (KT)) * 4) * 32 + l;                     \
                const uint2 wr0 = __ldg(&g_Brz[rb]);                              \
                const uint2 wr1 = __ldg(&g_Brz[rb + 32]);                         \
                const uint2 wz0 = __ldg(&g_Brz[rb + 64]);                         \
                const uint2 wz1 = __ldg(&g_Brz[rb + 96]);                         \
                mma_f16(aR[0][0], A0, wr0.x, wr0.y);                              \
                mma_f16(aR[1][0], A1, wr0.x, wr0.y);                              \
                mma_f16(aR[0][1], A0, wr1.x, wr1.y);                              \
                mma_f16(aR[1][1], A1, wr1.x, wr1.y);                              \
                mma_f16(aZ[0][0], A0, wz0.x, wz0.y);                              \
                mma_f16(aZ[1][0], A1, wz0.x, wz0.y);                              \
                mma_f16(aZ[0][1], A0, wz1.x, wz1.y);                              \
                mma_f16(aZ[1][1], A1, wz1.x, wz1.y);                              \
                const uint4 wi0 = __ldg(&g_Bn[rb]);                               \
                const uint4 wi1 = __ldg(&g_Bn[rb + 32]);                          \
                const uint4 wh0 = __ldg(&g_Bn[rb + 64]);                          \
                const uint4 wh1 = __ldg(&g_Bn[rb + 96]);                          \
                mma_pair(aIN[0][0], aIN[1][0], A0, A1, wi0);                      \
                mma_pair(aIN[0][1], aIN[1][1], A0, A1, wi1);                      \
                mma_pair(aHN[0][0], aHN[1][0], A0, A1, wh0);                      \
                mma_pair(aHN[0][1], aHN[1][1], A0, A1, wh1);                      \
            }
            KT1(0) KT1(1) KT1(2) KT1(3) KT1(4) KT1(5) KT1(6) KT1(7)
#undef KT1
        }

        // ---- epilogue: gates -> h_new (fp32 state), store frag ktile w ----
        const float* brp = (t == 0) ? g_br0 : g_br1;
        const float* bzp = (t == 0) ? g_bz0 : g_bz1;
        const float* bip = (t == 0) ? g_bin0 : g_bin1;
        float hn[2][2][4];
#pragma unroll
        for (int nt2 = 0; nt2 < 2; nt2++) {
            const int cb = 16 * w + 8 * nt2 + c2;
            const float2 brv = *(const float2*)&brp[cb];
            const float2 bzv = *(const float2*)&bzp[cb];
            const float2 biv = *(const float2*)&bip[cb];
            const float2 bhv = *(const float2*)&g_bhn[cb];
#pragma unroll
            for (int mt = 0; mt < 2; mt++)
#pragma unroll
                for (int e = 0; e < 4; e++) {
                    const float bR = (e & 1) ? brv.y : brv.x;
                    const float bZ = (e & 1) ? bzv.y : bzv.x;
                    const float bI = (e & 1) ? biv.y : biv.x;
                    const float bH = (e & 1) ? bhv.y : bhv.x;
                    float r = sigmoid_f(aR[mt][nt2][e] + bR);
                    float z = sigmoid_f(aZ[mt][nt2][e] + bZ);
                    float n = tanh_f(fmaf(r, aHN[mt][nt2][e] + bH,
                                          aIN[mt][nt2][e] + bI));
                    float hv = n + z * (hOld[mt][nt2][e] - n);
                    hOld[mt][nt2][e] = hv;
                    hn[mt][nt2][e] = hv;
                }
        }
#pragma unroll
        for (int mt = 0; mt < 2; mt++) {
            sA[nxt][w][mt][l] = make_uint4(
                f2h2(hn[mt][0][0], hn[mt][0][1]),
                f2h2(hn[mt][0][2], hn[mt][0][3]),
                f2h2(hn[mt][1][0], hn[mt][1][1]),
                f2h2(hn[mt][1][2], hn[mt][1][3]));
        }
        __syncthreads();   // ONLY barrier: h_new fragments visible

        // ---- y = h_new @ W_out^T + b_out : off the recurrence critical path
        // (next step's gate MMAs don't depend on y — weights are folded)
        float y[4] = {bo2.x, bo2.y, bo2.x, bo2.y};
#pragma unroll
        for (int kt = 0; kt < 8; kt++) {
            const uint4 Ah = sA[nxt][kt][mty][l];
            const uint4 wf = __ldg(&g_Wo[(kt * 4 + nty) * 32 + l]);
            mma_f16(y, Ah, wf.x, wf.y);
            mma_f16(y, Ah, wf.z, wf.w);
        }
        {
            const size_t row0 = (size_t)b0 + mty * 16 + r4;
            const int col = nty * 8 + c2;
            *(float2*)&out[(row0 * STEPS + t) * II + col]       = make_float2(y[0], y[1]);
            *(float2*)&out[((row0 + 8) * STEPS + t) * II + col] = make_float2(y[2], y[3]);
        }
    }
}

// ---------------------------------------------------------------------------
// Harness entry point
// ---------------------------------------------------------------------------
extern "C" void kernel_launch(void* const* d_in, const int* in_sizes, int n_in,
                              void* d_out, int out_size)
{
    const float* x     = (const float*)d_in[0];
    const float* h     = (const float*)d_in[1];
    const float* W_ih  = (const float*)d_in[2];
    const float* W_hh  = (const float*)d_in[3];
    const float* b_ih  = (const float*)d_in[4];
    const float* b_hh  = (const float*)d_in[5];
    const float* W_out = (const float*)d_in[6];
    const float* b_out = (const float*)d_in[7];
    float* out = (float*)d_out;

    pack1<<<194, 256>>>(W_ih, W_out, b_out);
    pack2<<<129, 256>>>(W_ih, W_hh, W_out, b_ih, b_hh);
    gru_kernel<<<BB / MT, NTH>>>(x, h, b_out, out);
}

// round 16
// speedup vs baseline: 8.8125x; 1.3695x over previous
#include <cuda_runtime.h>
#include <cuda_fp16.h>

// Problem constants
#define BB     16384
#define TT     60
#define II     32
#define HH     128
#define STEPS  30
#define SEQOFF 30

#define MT    32       // batch rows per CTA (2 m16 tiles)
#define NTH   256
#define NWARP 8

typedef unsigned int u32;

// ---------------------------------------------------------------------------
// Weight folding: for t>=1, x_t = y_{t-1} = h·Wo^T + bo, so gate pre-acts are
// pure functions of h:  Wcomb = W_ih @ W_out  [384x128],
//   r/z:  single merged matrix (W_hh + Wcomb), 1-pass fp16 (hi only)
//   n  :  aIN via Wcomb_n, aHN via W_hh_n — now ALSO 1-pass fp16 (hi only)
// Step 0 uses the original K=160 path (real x) with g_B (2-pass, R13 layout).
// ---------------------------------------------------------------------------
__device__ float g_Wcomb[384 * 128];
__device__ float g_bxo[384];

__device__ uint4 g_B[15360];    // t=0 weights: [(w*10+kt)*6+tau]*32+lane (hi,hi,lo,lo)
__device__ uint2 g_Brz[8192];   // t>=1 merged r/z: [(w*8+kt)*4+tau]*32+lane (hi only)
__device__ uint2 g_Bn[8192];    // t>=1 n: tau 0,1=in(Wcomb_n) 2,3=hn(W_hh_n), hi only
__device__ uint4 g_Wo[1024];    // y weights: [(kt*4+nt)*32+lane], hi/lo (2-pass)
__device__ float g_br0[128], g_bz0[128], g_bin0[128];   // t=0 biases
__device__ float g_br1[128], g_bz1[128], g_bin1[128];   // t>=1 (Wx·bo folded)
__device__ float g_bhn[128];

__device__ __forceinline__ u32 f2h2(float a, float b) {
    __half2 h = __floats2half2_rn(a, b);   // a -> low, b -> high
    return *(u32*)&h;
}
__device__ __forceinline__ void packw(float a, float b, u32& hi, u32& lo) {
    __half ha = __float2half_rn(a), hb = __float2half_rn(b);
    hi = ((u32)__half_as_ushort(hb) << 16) | (u32)__half_as_ushort(ha);
    lo = f2h2(a - __half2float(ha), b - __half2float(hb));
}

// pack stage 1: Wcomb = W_ih @ W_out, bxo = W_ih @ b_out
__global__ void pack1(const float* __restrict__ W_ih,
                      const float* __restrict__ W_out,
                      const float* __restrict__ b_out)
{
    int idx = blockIdx.x * blockDim.x + threadIdx.x;
    if (idx < 384 * 128) {
        int col = idx >> 7, j = idx & 127;
        float s = 0.f;
#pragma unroll
        for (int i = 0; i < 32; i++)
            s += W_ih[col * 32 + i] * W_out[i * 128 + j];
        g_Wcomb[idx] = s;
    }
    int i2 = idx - 49152;
    if (i2 >= 0 && i2 < 384) {
        float s = 0.f;
#pragma unroll
        for (int i = 0; i < 32; i++)
            s += W_ih[i2 * 32 + i] * b_out[i];
        g_bxo[i2] = s;
    }
}

// pack stage 2: all fragment-packed weight arrays + biases
__global__ void pack2(const float* __restrict__ W_ih,
                      const float* __restrict__ W_hh,
                      const float* __restrict__ W_out,
                      const float* __restrict__ b_ih,
                      const float* __restrict__ b_hh)
{
    int idx = blockIdx.x * blockDim.x + threadIdx.x;
    if (idx < 15360) {                       // t=0 gate fragments (K=160, 2-pass)
        int lane = idx & 31, tau = (idx >> 5) % 6, kt = (idx / 192) % 10, w = idx / 1920;
        int gate = tau >> 1, nt2 = tau & 1;
        int n = lane >> 2, tg = lane & 3;
        int col = gate * 128 + 16 * w + 8 * nt2 + n;
        float e[4];
#pragma unroll
        for (int q = 0; q < 4; q++) {
            int k = kt * 16 + 2 * tg + (q & 1) + 8 * (q >> 1);
            e[q] = (k < 32) ? W_ih[col * 32 + k] : W_hh[col * 128 + (k - 32)];
        }
        u32 hi0, hi1, lo0, lo1;
        packw(e[0], e[1], hi0, lo0);
        packw(e[2], e[3], hi1, lo1);
        g_B[idx] = make_uint4(hi0, hi1, lo0, lo1);
    }
    int ib = idx - 15360;
    if (ib >= 0 && ib < 8192) {              // merged r/z fragments (hi only)
        int lane = ib & 31, tau = (ib >> 5) & 3, kt = (ib >> 7) & 7, w = ib >> 10;
        int gate = tau >> 1, nt2 = tau & 1;
        int n = lane >> 2, tg = lane & 3;
        int col = gate * 128 + 16 * w + 8 * nt2 + n;
        float e[4];
#pragma unroll
        for (int q = 0; q < 4; q++) {
            int k = kt * 16 + 2 * tg + (q & 1) + 8 * (q >> 1);
            e[q] = W_hh[col * 128 + k] + g_Wcomb[col * 128 + k];
        }
        g_Brz[ib] = make_uint2(f2h2(e[0], e[1]), f2h2(e[2], e[3]));
    }
    int in_ = idx - 23552;
    if (in_ >= 0 && in_ < 8192) {            // n fragments (hi only, 1-pass)
        int lane = in_ & 31, tau = (in_ >> 5) & 3, kt = (in_ >> 7) & 7, w = in_ >> 10;
        int isIn = (tau < 2), nt2 = tau & 1;
        int n = lane >> 2, tg = lane & 3;
        int col = 256 + 16 * w + 8 * nt2 + n;
        float e[4];
#pragma unroll
        for (int q = 0; q < 4; q++) {
            int k = kt * 16 + 2 * tg + (q & 1) + 8 * (q >> 1);
            e[q] = isIn ? g_Wcomb[col * 128 + k] : W_hh[col * 128 + k];
        }
        g_Bn[in_] = make_uint2(f2h2(e[0], e[1]), f2h2(e[2], e[3]));
    }
    int iw = idx - 31744;
    if (iw >= 0 && iw < 1024) {              // W_out fragments (hi/lo, 2-pass)
        int lane = iw & 31, nt = (iw >> 5) & 3, kt = iw >> 7;
        int i = nt * 8 + (lane >> 2), tg = lane & 3;
        float e[4];
#pragma unroll
        for (int q = 0; q < 4; q++) {
            int k = kt * 16 + 2 * tg + (q & 1) + 8 * (q >> 1);
            e[q] = W_out[i * 128 + k];
        }
        u32 hi0, hi1, lo0, lo1;
        packw(e[0], e[1], hi0, lo0);
        packw(e[2], e[3], hi1, lo1);
        g_Wo[iw] = make_uint4(hi0, hi1, lo0, lo1);
    }
    int i4 = idx - 32768;
    if (i4 >= 0 && i4 < 128) {               // biases
        float br = b_ih[i4]       + b_hh[i4];
        float bz = b_ih[128 + i4] + b_hh[128 + i4];
        float bi = b_ih[256 + i4];
        g_br0[i4]  = br;  g_br1[i4]  = br + g_bxo[i4];
        g_bz0[i4]  = bz;  g_bz1[i4]  = bz + g_bxo[128 + i4];
        g_bin0[i4] = bi;  g_bin1[i4] = bi + g_bxo[256 + i4];
        g_bhn[i4]  = b_hh[256 + i4];
    }
}

__device__ __forceinline__ void mma_f16(float (&d)[4], const uint4& a, u32 b0, u32 b1) {
    asm("mma.sync.aligned.m16n8k16.row.col.f32.f16.f16.f32 "
        "{%0,%1,%2,%3},{%4,%5,%6,%7},{%8,%9},{%0,%1,%2,%3};"
        : "+f"(d[0]), "+f"(d[1]), "+f"(d[2]), "+f"(d[3])
        : "r"(a.x), "r"(a.y), "r"(a.z), "r"(a.w), "r"(b0), "r"(b1));
}

// 2-pass (Wh + Wl) MMA into two m-tiles' accumulators
__device__ __forceinline__ void mma_pair(float (&d0)[4], float (&d1)[4],
                                         const uint4& A0, const uint4& A1,
                                         const uint4& wf) {
    mma_f16(d0, A0, wf.x, wf.y);
    mma_f16(d0, A0, wf.z, wf.w);
    mma_f16(d1, A1, wf.x, wf.y);
    mma_f16(d1, A1, wf.z, wf.w);
}

// MUFU.TANH-based activations: 1 MUFU each (vs 2 for the exp/div forms)
__device__ __forceinline__ float tanh_f(float v) {
    float r; asm("tanh.approx.f32 %0, %1;" : "=f"(r) : "f"(v)); return r;
}
__device__ __forceinline__ float sigmoid_f(float v) {
    float t; asm("tanh.approx.f32 %0, %1;" : "=f"(t) : "f"(0.5f * v));
    return fmaf(0.5f, t, 0.5f);
}

// ---------------------------------------------------------------------------
// Recurrent kernel. CTA = 32 batch rows, 8 warps, 30 steps, ONE barrier/step.
// sA: h fragments (fp16), double-buffered, 8 ktiles (K=128). Warp w owns gate
// cols [16w,16w+16) == h ktile w. y-GEMM is off the recurrence critical path.
// ---------------------------------------------------------------------------
__global__ __launch_bounds__(NTH, 2)
void gru_kernel(const float* __restrict__ x,
                const float* __restrict__ h0,
                const float* __restrict__ b_out,
                float* __restrict__ out)
{
    __shared__ uint4 sA[2][8][2][32];   // 16 KB
    __shared__ uint4 sX[2][2][32];      // 2 KB  (x0 fragments, t=0 only)

    const int tid = threadIdx.x;
    const int w   = tid >> 5;
    const int l   = tid & 31;
    const int b0  = blockIdx.x * MT;
    const int r4  = l >> 2;
    const int c2  = (l & 3) * 2;

    // ---- prologue: h0 fragments (warp w -> ktile w) ----
#pragma unroll
    for (int mt = 0; mt < 2; mt++) {
        float e[8];
#pragma unroll
        for (int q = 0; q < 4; q++) {
            int row = b0 + mt * 16 + r4 + 8 * (q & 1);
            int k   = w * 16 + c2 + 8 * (q >> 1);
            float2 v = *(const float2*)&h0[(size_t)row * HH + k];
            e[2 * q] = v.x; e[2 * q + 1] = v.y;
        }
        sA[0][w][mt][l] = make_uint4(f2h2(e[0], e[1]), f2h2(e[2], e[3]),
                                     f2h2(e[4], e[5]), f2h2(e[6], e[7]));
    }
    // x0 fragments: warps 0-3 -> (kt = w>>1, mt = w&1)
    if (w < 4) {
        const int kt = w >> 1, mt = w & 1;
        float e[8];
#pragma unroll
        for (int q = 0; q < 4; q++) {
            int row = b0 + mt * 16 + r4 + 8 * (q & 1);
            int k   = kt * 16 + c2 + 8 * (q >> 1);
            float2 v = *(const float2*)&x[(size_t)row * (TT * II) + SEQOFF * II + k];
            e[2 * q] = v.x; e[2 * q + 1] = v.y;
        }
        sX[kt][mt][l] = make_uint4(f2h2(e[0], e[1]), f2h2(e[2], e[3]),
                                   f2h2(e[4], e[5]), f2h2(e[6], e[7]));
    }

    // ---- persistent fp32 hidden state for this warp's 16 cols ----
    float hOld[2][2][4];
#pragma unroll
    for (int mt = 0; mt < 2; mt++)
#pragma unroll
        for (int nt2 = 0; nt2 < 2; nt2++)
#pragma unroll
            for (int rh = 0; rh < 2; rh++) {
                int row = b0 + mt * 16 + r4 + 8 * rh;
                int col = 16 * w + 8 * nt2 + c2;
                float2 v = *(const float2*)&h0[(size_t)row * HH + col];
                hOld[mt][nt2][2 * rh]     = v.x;
                hOld[mt][nt2][2 * rh + 1] = v.y;
            }

    const int mty = w >> 2, nty = w & 3;   // this warp's y-output tile
    const float2 bo2 = *(const float2*)&b_out[nty * 8 + c2];
    __syncthreads();

    for (int t = 0; t < STEPS; t++) {
        const int cur = t & 1, nxt = cur ^ 1;

        float aR[2][2][4], aZ[2][2][4], aIN[2][2][4], aHN[2][2][4];
#pragma unroll
        for (int mt = 0; mt < 2; mt++)
#pragma unroll
            for (int nt2 = 0; nt2 < 2; nt2++)
#pragma unroll
                for (int e = 0; e < 4; e++) {
                    aR[mt][nt2][e] = 0.f; aZ[mt][nt2][e] = 0.f;
                    aIN[mt][nt2][e] = 0.f; aHN[mt][nt2][e] = 0.f;
                }

        if (t == 0) {
            // original K=160 path (real x), 2-pass everywhere
#pragma unroll
            for (int kt = 0; kt < 10; kt++) {
                uint4 A0, A1;
                if (kt < 2) { A0 = sX[kt][0][l];     A1 = sX[kt][1][l]; }
                else        { A0 = sA[0][kt - 2][0][l]; A1 = sA[0][kt - 2][1][l]; }
                const int gb = ((w * 10 + kt) * 6) * 32 + l;
                mma_pair(aR[0][0], aR[1][0], A0, A1, __ldg(&g_B[gb]));
                mma_pair(aR[0][1], aR[1][1], A0, A1, __ldg(&g_B[gb + 32]));
                mma_pair(aZ[0][0], aZ[1][0], A0, A1, __ldg(&g_B[gb + 64]));
                mma_pair(aZ[0][1], aZ[1][1], A0, A1, __ldg(&g_B[gb + 96]));
                if (kt < 2) {
                    mma_pair(aIN[0][0], aIN[1][0], A0, A1, __ldg(&g_B[gb + 128]));
                    mma_pair(aIN[0][1], aIN[1][1], A0, A1, __ldg(&g_B[gb + 160]));
                } else {
                    mma_pair(aHN[0][0], aHN[1][0], A0, A1, __ldg(&g_B[gb + 128]));
                    mma_pair(aHN[0][1], aHN[1][1], A0, A1, __ldg(&g_B[gb + 160]));
                }
            }
        } else {
            // merged K=128 path: ALL gates 1-pass (16 mma/ktile)
#define KT1(KT)                                                                   \
            {                                                                     \
                const uint4 A0 = sA[cur][KT][0][l];                               \
                const uint4 A1 = sA[cur][KT][1][l];                               \
                const int rb = ((w * 8 + (KT)) * 4) * 32 + l;                     \
                const uint2 wr0 = __ldg(&g_Brz[rb]);                              \
                const uint2 wr1 = __ldg(&g_Brz[rb + 32]);                         \
                const uint2 wz0 = __ldg(&g_Brz[rb + 64]);                         \
                const uint2 wz1 = __ldg(&g_Brz[rb + 96]);                         \
                mma_f16(aR[0][0], A0, wr0.x, wr0.y);                              \
                mma_f16(aR[1][0], A1, wr0.x, wr0.y);                              \
                mma_f16(aR[0][1], A0, wr1.x, wr1.y);                              \
                mma_f16(aR[1][1], A1, wr1.x, wr1.y);                              \
                mma_f16(aZ[0][0], A0, wz0.x, wz0.y);                              \
                mma_f16(aZ[1][0], A1, wz0.x, wz0.y);                              \
                mma_f16(aZ[0][1], A0, wz1.x, wz1.y);                              \
                mma_f16(aZ[1][1], A1, wz1.x, wz1.y);                              \
                const uint2 wi0 = __ldg(&g_Bn[rb]);                               \
                const uint2 wi1 = __ldg(&g_Bn[rb + 32]);                          \
                const uint2 wh0 = __ldg(&g_Bn[rb + 64]);                          \
                const uint2 wh1 = __ldg(&g_Bn[rb + 96]);                          \
                mma_f16(aIN[0][0], A0, wi0.x, wi0.y);                             \
                mma_f16(aIN[1][0], A1, wi0.x, wi0.y);                             \
                mma_f16(aIN[0][1], A0, wi1.x, wi1.y);                             \
                mma_f16(aIN[1][1], A1, wi1.x, wi1.y);                             \
                mma_f16(aHN[0][0], A0, wh0.x, wh0.y);                             \
                mma_f16(aHN[1][0], A1, wh0.x, wh0.y);                             \
                mma_f16(aHN[0][1], A0, wh1.x, wh1.y);                             \
                mma_f16(aHN[1][1], A1, wh1.x, wh1.y);                             \
            }
            KT1(0) KT1(1) KT1(2) KT1(3) KT1(4) KT1(5) KT1(6) KT1(7)
#undef KT1
        }

        // ---- epilogue: gates -> h_new (fp32 state), store frag ktile w ----
        const float* brp = (t == 0) ? g_br0 : g_br1;
        const float* bzp = (t == 0) ? g_bz0 : g_bz1;
        const float* bip = (t == 0) ? g_bin0 : g_bin1;
        float hn[2][2][4];
#pragma unroll
        for (int nt2 = 0; nt2 < 2; nt2++) {
            const int cb = 16 * w + 8 * nt2 + c2;
            const float2 brv = *(const float2*)&brp[cb];
            const float2 bzv = *(const float2*)&bzp[cb];
            const float2 biv = *(const float2*)&bip[cb];
            const float2 bhv = *(const float2*)&g_bhn[cb];
#pragma unroll
            for (int mt = 0; mt < 2; mt++)
#pragma unroll
                for (int e = 0; e < 4; e++) {
                    const float bR = (e & 1) ? brv.y : brv.x;
                    const float bZ = (e & 1) ? bzv.y : bzv.x;
                    const float bI = (e & 1) ? biv.y : biv.x;
                    const float bH = (e & 1) ? bhv.y : bhv.x;
                    float r = sigmoid_f(aR[mt][nt2][e] + bR);
                    float z = sigmoid_f(aZ[mt][nt2][e] + bZ);
                    float n = tanh_f(fmaf(r, aHN[mt][nt2][e] + bH,
                                          aIN[mt][nt2][e] + bI));
                    float hv = n + z * (hOld[mt][nt2][e] - n);
                    hOld[mt][nt2][e] = hv;
                    hn[mt][nt2][e] = hv;
                }
        }
#pragma unroll
        for (int mt = 0; mt < 2; mt++) {
            sA[nxt][w][mt][l] = make_uint4(
                f2h2(hn[mt][0][0], hn[mt][0][1]),
                f2h2(hn[mt][0][2], hn[mt][0][3]),
                f2h2(hn[mt][1][0], hn[mt][1][1]),
                f2h2(hn[mt][1][2], hn[mt][1][3]));
        }
        __syncthreads();   // ONLY barrier: h_new fragments visible

        // ---- y = h_new @ W_out^T + b_out : off the recurrence critical path
        float y[4] = {bo2.x, bo2.y, bo2.x, bo2.y};
#pragma unroll
        for (int kt = 0; kt < 8; kt++) {
            const uint4 Ah = sA[nxt][kt][mty][l];
            const uint4 wf = __ldg(&g_Wo[(kt * 4 + nty) * 32 + l]);
            mma_f16(y, Ah, wf.x, wf.y);
            mma_f16(y, Ah, wf.z, wf.w);
        }
        {
            const size_t row0 = (size_t)b0 + mty * 16 + r4;
            const int col = nty * 8 + c2;
            *(float2*)&out[(row0 * STEPS + t) * II + col]       = make_float2(y[0], y[1]);
            *(float2*)&out[((row0 + 8) * STEPS + t) * II + col] = make_float2(y[2], y[3]);
        }
    }
}

// ---------------------------------------------------------------------------
// Harness entry point
// ---------------------------------------------------------------------------
extern "C" void kernel_launch(void* const* d_in, const int* in_sizes, int n_in,
                              void* d_out, int out_size)
{
    const float* x     = (const float*)d_in[0];
    const float* h     = (const float*)d_in[1];
    const float* W_ih  = (const float*)d_in[2];
    const float* W_hh  = (const float*)d_in[3];
    const float* b_ih  = (const float*)d_in[4];
    const float* b_hh  = (const float*)d_in[5];
    const float* W_out = (const float*)d_in[6];
    const float* b_out = (const float*)d_in[7];
    float* out = (float*)d_out;

    pack1<<<194, 256>>>(W_ih, W_out, b_out);
    pack2<<<129, 256>>>(W_ih, W_hh, W_out, b_ih, b_hh);
    gru_kernel<<<BB / MT, NTH>>>(x, h, b_out, out);
}